// round 5
// baseline (speedup 1.0000x reference)
#include <cuda_runtime.h>
#include <cuda_bf16.h>
#include <math.h>
#include <cstdint>

// Problem constants
#define TSEQ 2048
#define DMODEL 2048
#define HQ 32
#define HKV 8
#define DHEAD 64
#define DKV (HKV * DHEAD)   // 512

// ---------------------------------------------------------------------------
// Device-global scratch (allocation-free rule). All bf16 arrays 16B-aligned.
// ---------------------------------------------------------------------------
__device__ float g_q[TSEQ * DMODEL];                       // fp32 Q pre-rope
__device__ float g_k[TSEQ * DKV];                          // fp32 K pre-rope
__device__ __align__(16) __nv_bfloat16 g_xh[TSEQ * DMODEL], g_xl[TSEQ * DMODEL];
__device__ __align__(16) __nv_bfloat16 g_wh[3072 * DMODEL], g_wl[3072 * DMODEL];
__device__ __align__(16) __nv_bfloat16 g_woh[DMODEL * DMODEL], g_wol[DMODEL * DMODEL];
__device__ __align__(16) __nv_bfloat16 g_qh[TSEQ * DMODEL], g_ql[TSEQ * DMODEL];
__device__ __align__(16) __nv_bfloat16 g_kh[TSEQ * DKV], g_kl[TSEQ * DKV];
__device__ __align__(16) __nv_bfloat16 g_vh[TSEQ * DKV], g_vl[TSEQ * DKV];
__device__ __align__(16) __nv_bfloat16 g_ah[TSEQ * DMODEL], g_al[TSEQ * DMODEL];

// ===========================================================================
// Warp-MMA / async-copy helpers (sm_80+ baseline; no sm_103a-only features)
// ===========================================================================
__device__ __forceinline__ uint32_t smem_u32(const void* p) {
    uint32_t a;
    asm("{ .reg .u64 t; cvta.to.shared.u64 t, %1; cvt.u32.u64 %0, t; }"
        : "=r"(a) : "l"(p));
    return a;
}
__device__ __forceinline__ void ldsm4(uint32_t* r, uint32_t a) {
    asm volatile("ldmatrix.sync.aligned.m8n8.x4.shared.b16 {%0,%1,%2,%3}, [%4];"
                 : "=r"(r[0]), "=r"(r[1]), "=r"(r[2]), "=r"(r[3]) : "r"(a));
}
__device__ __forceinline__ void ldsm4t(uint32_t* r, uint32_t a) {
    asm volatile("ldmatrix.sync.aligned.m8n8.x4.trans.shared.b16 {%0,%1,%2,%3}, [%4];"
                 : "=r"(r[0]), "=r"(r[1]), "=r"(r[2]), "=r"(r[3]) : "r"(a));
}
__device__ __forceinline__ void mma_bf16(float* c, const uint32_t* a,
                                         uint32_t b0, uint32_t b1) {
    asm volatile(
        "mma.sync.aligned.m16n8k16.row.col.f32.bf16.bf16.f32 "
        "{%0,%1,%2,%3}, {%4,%5,%6,%7}, {%8,%9}, {%0,%1,%2,%3};"
        : "+f"(c[0]), "+f"(c[1]), "+f"(c[2]), "+f"(c[3])
        : "r"(a[0]), "r"(a[1]), "r"(a[2]), "r"(a[3]), "r"(b0), "r"(b1));
}
__device__ __forceinline__ void cp_async16(uint32_t dst, const void* src) {
    asm volatile("cp.async.cg.shared.global [%0], [%1], 16;" :: "r"(dst), "l"(src));
}
#define CP_COMMIT() asm volatile("cp.async.commit_group;" ::: "memory")
#define CP_WAIT(N)  asm volatile("cp.async.wait_group %0;" :: "n"(N) : "memory")

__device__ __forceinline__ uint32_t u32of(__nv_bfloat162 h) {
    return *reinterpret_cast<uint32_t*>(&h);
}
__device__ __forceinline__ void cvt_hilo(float x, float y, uint32_t& hi, uint32_t& lo) {
    __nv_bfloat162 h = __floats2bfloat162_rn(x, y);
    float2 hf = __bfloat1622float2(h);
    __nv_bfloat162 l = __floats2bfloat162_rn(x - hf.x, y - hf.y);
    hi = u32of(h);
    lo = u32of(l);
}

// ---------------------------------------------------------------------------
// fp32 -> hi/lo bf16 conversion kernel (vectorized by 4)
// ---------------------------------------------------------------------------
__global__ void cvt_kernel(const float* __restrict__ src,
                           __nv_bfloat16* __restrict__ dh,
                           __nv_bfloat16* __restrict__ dl, int n) {
    int i = (blockIdx.x * blockDim.x + threadIdx.x) * 4;
    if (i >= n) return;
    float4 f = *reinterpret_cast<const float4*>(src + i);
    uint32_t h0, l0, h1, l1;
    cvt_hilo(f.x, f.y, h0, l0);
    cvt_hilo(f.z, f.w, h1, l1);
    *reinterpret_cast<uint32_t*>(dh + i)     = h0;
    *reinterpret_cast<uint32_t*>(dh + i + 2) = h1;
    *reinterpret_cast<uint32_t*>(dl + i)     = l0;
    *reinterpret_cast<uint32_t*>(dl + i + 2) = l1;
}

// ---------------------------------------------------------------------------
// RoPE: fp32 in -> rotated hi/lo bf16 out
// ---------------------------------------------------------------------------
__global__ void rope_cvt_kernel(const float* __restrict__ src,
                                const float* __restrict__ cosb,
                                const float* __restrict__ sinb,
                                __nv_bfloat16* __restrict__ dh,
                                __nv_bfloat16* __restrict__ dl, int H) {
    int idx = blockIdx.x * blockDim.x + threadIdx.x;
    int total = TSEQ * H * 32;
    if (idx >= total) return;
    int i = idx & 31;
    int h = (idx >> 5) % H;
    int t = idx / (32 * H);
    float c = cosb[t * 32 + i];
    float s = sinb[t * 32 + i];
    size_t off = ((size_t)t * H + h) * DHEAD + 2 * i;
    float x0 = src[off], x1 = src[off + 1];
    float o0 = x0 * c - x1 * s;
    float o1 = x0 * s + x1 * c;
    uint32_t hh, ll;
    cvt_hilo(o0, o1, hh, ll);
    *reinterpret_cast<uint32_t*>(dh + off) = hh;
    *reinterpret_cast<uint32_t*>(dl + off) = ll;
}

// ===========================================================================
// Projection GEMM (bf16 hi/lo inputs, 3-term HMMA, cp.async 2-stage pipeline)
// C[128,128] tile of A[M,2048] · B[N,2048]^T. 256 thr = 8 warps, 64x32/warp.
// ===========================================================================
#define GST 40                       // smem row stride in halves (80B)
#define TILE_H (128 * GST)           // halves per tile buffer (5120)
#define STAGE_H (4 * TILE_H)         // Ah,Al,Bh,Bl per stage
constexpr int GEMM_SMEM_BYTES = 2 * STAGE_H * 2;   // 81920

__device__ __forceinline__ void gemm_loads(uint32_t sb, int stage,
                                           const __nv_bfloat16* Ah,
                                           const __nv_bfloat16* Al,
                                           const __nv_bfloat16* Bh,
                                           const __nv_bfloat16* Bl,
                                           int k0, int tid) {
    const __nv_bfloat16* bases[4] = {Ah, Al, Bh, Bl};
    uint32_t dbase = sb + (uint32_t)stage * STAGE_H * 2;
#pragma unroll
    for (int t = 0; t < 4; ++t) {
#pragma unroll
        for (int it = 0; it < 2; ++it) {
            int slot = tid + it * 256;      // 512 slots: 128 rows x 4 chunks
            int row = slot >> 2;
            int q = slot & 3;
            const void* src = bases[t] + (size_t)row * 2048 + k0 + q * 8;
            uint32_t dst = dbase + (uint32_t)(t * TILE_H + row * GST + q * 8) * 2;
            cp_async16(dst, src);
        }
    }
}

__device__ void gemm_body(const __nv_bfloat16* __restrict__ Ah,
                          const __nv_bfloat16* __restrict__ Al,
                          const __nv_bfloat16* __restrict__ Bh,
                          const __nv_bfloat16* __restrict__ Bl,
                          float* Cf, __nv_bfloat16* Cvh, __nv_bfloat16* Cvl,
                          int ldc, int vout) {
    extern __shared__ uint16_t sm16[];
    uint32_t sb = smem_u32(sm16);
    int tid = threadIdx.x;
    int lane = tid & 31;
    int wid = tid >> 5;
    int m0 = (wid & 1) * 64;
    int n0 = (wid >> 1) * 32;

    float acc[4][4][4];
#pragma unroll
    for (int i = 0; i < 4; ++i)
#pragma unroll
        for (int j = 0; j < 4; ++j)
#pragma unroll
            for (int q = 0; q < 4; ++q) acc[i][j][q] = 0.0f;

    gemm_loads(sb, 0, Ah, Al, Bh, Bl, 0, tid);
    CP_COMMIT();

    for (int i = 0; i < 64; ++i) {
        int s = i & 1;
        if (i < 63) {
            gemm_loads(sb, s ^ 1, Ah, Al, Bh, Bl, (i + 1) * 32, tid);
            CP_COMMIT();
            CP_WAIT(1);
        } else {
            CP_WAIT(0);
        }
        __syncthreads();

        uint32_t aAh = sb + (uint32_t)s * STAGE_H * 2;
        uint32_t aAl = aAh + TILE_H * 2;
        uint32_t aBh = aAl + TILE_H * 2;
        uint32_t aBl = aBh + TILE_H * 2;

#pragma unroll
        for (int kk = 0; kk < 2; ++kk) {
            uint32_t ah[4][4], al[4][4];
            int rA = m0 + (lane & 15);
            int cA = kk * 16 + ((lane >> 4) << 3);
#pragma unroll
            for (int i2 = 0; i2 < 4; ++i2) {
                uint32_t off = (uint32_t)(((rA + 16 * i2) * GST + cA) * 2);
                ldsm4(ah[i2], aAh + off);
                ldsm4(al[i2], aAl + off);
            }
            uint32_t bh[2][4], bl[2][4];
            int rB = n0 + (lane & 7) + ((lane >> 3) & 1) * 8;
            int cB = kk * 16 + ((lane >> 4) << 3);
#pragma unroll
            for (int jp = 0; jp < 2; ++jp) {
                uint32_t off = (uint32_t)(((rB + 16 * jp) * GST + cB) * 2);
                ldsm4(bh[jp], aBh + off);
                ldsm4(bl[jp], aBl + off);
            }
#pragma unroll
            for (int i2 = 0; i2 < 4; ++i2)
#pragma unroll
                for (int jp = 0; jp < 2; ++jp) {
                    mma_bf16(acc[i2][2 * jp],     ah[i2], bh[jp][0], bh[jp][2]);
                    mma_bf16(acc[i2][2 * jp],     ah[i2], bl[jp][0], bl[jp][2]);
                    mma_bf16(acc[i2][2 * jp],     al[i2], bh[jp][0], bh[jp][2]);
                    mma_bf16(acc[i2][2 * jp + 1], ah[i2], bh[jp][1], bh[jp][3]);
                    mma_bf16(acc[i2][2 * jp + 1], ah[i2], bl[jp][1], bl[jp][3]);
                    mma_bf16(acc[i2][2 * jp + 1], al[i2], bh[jp][1], bh[jp][3]);
                }
        }
        __syncthreads();
    }

    int r = m0 + (lane >> 2);
    int cq = 2 * (lane & 3);
    if (!vout) {
#pragma unroll
        for (int i = 0; i < 4; ++i)
#pragma unroll
            for (int j = 0; j < 4; ++j) {
                int row = r + 16 * i;
                int col = n0 + 8 * j + cq;
                *reinterpret_cast<float2*>(Cf + (size_t)row * ldc + col) =
                    make_float2(acc[i][j][0], acc[i][j][1]);
                *reinterpret_cast<float2*>(Cf + (size_t)(row + 8) * ldc + col) =
                    make_float2(acc[i][j][2], acc[i][j][3]);
            }
    } else {
#pragma unroll
        for (int i = 0; i < 4; ++i)
#pragma unroll
            for (int j = 0; j < 4; ++j) {
                int row = r + 16 * i;
                int col = n0 + 8 * j + cq;
                uint32_t hh, ll;
                cvt_hilo(acc[i][j][0], acc[i][j][1], hh, ll);
                *reinterpret_cast<uint32_t*>(Cvh + (size_t)row * ldc + col) = hh;
                *reinterpret_cast<uint32_t*>(Cvl + (size_t)row * ldc + col) = ll;
                cvt_hilo(acc[i][j][2], acc[i][j][3], hh, ll);
                *reinterpret_cast<uint32_t*>(Cvh + (size_t)(row + 8) * ldc + col) = hh;
                *reinterpret_cast<uint32_t*>(Cvl + (size_t)(row + 8) * ldc + col) = ll;
            }
    }
}

// QKV projection: N = 2048 (Q) + 512 (K) + 512 (V, direct hi/lo bf16 out)
__global__ __launch_bounds__(256) void qkv_hmma() {
    int bm = blockIdx.y * 128;
    int bn = blockIdx.x * 128;
    const __nv_bfloat16* Ah = g_xh + (size_t)bm * DMODEL;
    const __nv_bfloat16* Al = g_xl + (size_t)bm * DMODEL;
    const __nv_bfloat16* Bh = g_wh + (size_t)bn * DMODEL;
    const __nv_bfloat16* Bl = g_wl + (size_t)bn * DMODEL;
    if (bn < 2048) {
        gemm_body(Ah, Al, Bh, Bl, g_q + (size_t)bm * DMODEL + bn,
                  nullptr, nullptr, DMODEL, 0);
    } else if (bn < 2560) {
        gemm_body(Ah, Al, Bh, Bl, g_k + (size_t)bm * DKV + (bn - 2048),
                  nullptr, nullptr, DKV, 0);
    } else {
        gemm_body(Ah, Al, Bh, Bl, nullptr,
                  g_vh + (size_t)bm * DKV + (bn - 2560),
                  g_vl + (size_t)bm * DKV + (bn - 2560), DKV, 1);
    }
}

__global__ __launch_bounds__(256) void out_hmma(float* __restrict__ out) {
    int bm = blockIdx.y * 128;
    int bn = blockIdx.x * 128;
    gemm_body(g_ah + (size_t)bm * DMODEL, g_al + (size_t)bm * DMODEL,
              g_woh + (size_t)bn * DMODEL, g_wol + (size_t)bn * DMODEL,
              out + (size_t)bm * DMODEL + bn, nullptr, nullptr, DMODEL, 0);
}

// ===========================================================================
// FA2-style causal GQA attention, bf16 hi/lo inputs (no mainloop conversion).
// Grid (T/64, HQ), 128 threads (4 warps), 16 q-rows/warp, BS=64.
// ===========================================================================
#define AST 72   // smem row stride in halves (144B)
constexpr int ATTN_SMEM_BYTES = 6 * 64 * AST * 2;   // 55296

__global__ __launch_bounds__(128, 3) void attn_hmma() {
    extern __shared__ uint16_t sm16[];
    uint16_t* sQh = sm16;
    uint16_t* sQl = sQh + 64 * AST;
    uint16_t* sKh = sQl + 64 * AST;
    uint16_t* sKl = sKh + 64 * AST;
    uint16_t* sVh = sKl + 64 * AST;
    uint16_t* sVl = sVh + 64 * AST;
    uint32_t aQh = smem_u32(sQh), aQl = smem_u32(sQl);
    uint32_t aKh = smem_u32(sKh), aKl = smem_u32(sKl);
    uint32_t aVh = smem_u32(sVh), aVl = smem_u32(sVl);

    int tid = threadIdx.x;
    int lane = tid & 31;
    int w = tid >> 5;
    int qt = blockIdx.x;
    int h = blockIdx.y;
    int kvh = h >> 2;
    const float SCALE = 0.125f;

    // Load Q tile (bf16 hi/lo, 64 x 64)
    {
        const __nv_bfloat16* qsrc[2] = {g_qh, g_ql};
        uint16_t* qdst[2] = {sQh, sQl};
#pragma unroll
        for (int it = 0; it < 8; ++it) {
            int slot = tid + it * 128;       // 1024 slots
            int t = slot >> 9;
            int r = (slot >> 3) & 63;
            int q = slot & 7;
            const __nv_bfloat16* src =
                qsrc[t] + (size_t)(qt * 64 + r) * DMODEL + h * DHEAD + q * 8;
            *reinterpret_cast<uint4*>(qdst[t] + r * AST + q * 8) =
                *reinterpret_cast<const uint4*>(src);
        }
    }

    float m0 = -1e30f, m1 = -1e30f, l0 = 0.0f, l1 = 0.0f;
    float oac[8][4];
#pragma unroll
    for (int j = 0; j < 8; ++j)
#pragma unroll
        for (int q = 0; q < 4; ++q) oac[j][q] = 0.0f;

    for (int st = 0; st <= qt; ++st) {
        __syncthreads();    // previous PV (and initial Q store) complete
        // Load K/V tiles (bf16 hi/lo, 64 x 64 each)
        {
            const __nv_bfloat16* srcs[4] = {g_kh, g_kl, g_vh, g_vl};
            uint16_t* dsts[4] = {sKh, sKl, sVh, sVl};
#pragma unroll
            for (int it = 0; it < 16; ++it) {
                int slot = tid + it * 128;   // 2048 slots
                int t = slot >> 9;
                int r = (slot >> 3) & 63;
                int q = slot & 7;
                const __nv_bfloat16* src =
                    srcs[t] + (size_t)(st * 64 + r) * DKV + kvh * DHEAD + q * 8;
                *reinterpret_cast<uint4*>(dsts[t] + r * AST + q * 8) =
                    *reinterpret_cast<const uint4*>(src);
            }
        }
        __syncthreads();

        // ---- S = Q K^T (3-term hi/lo), Q frags re-loaded from smem ----
        float sa[8][4];
#pragma unroll
        for (int j = 0; j < 8; ++j)
#pragma unroll
            for (int q = 0; q < 4; ++q) sa[j][q] = 0.0f;

        int rQ = 16 * w + (lane & 15);
        int rB = (lane & 7) + ((lane >> 3) & 1) * 8;
        int cF = ((lane >> 4) << 3);
#pragma unroll
        for (int kk = 0; kk < 4; ++kk) {
            uint32_t qh[4], ql[4];
            uint32_t qoff = (uint32_t)((rQ * AST + cF + 16 * kk) * 2);
            ldsm4(qh, aQh + qoff);
            ldsm4(ql, aQl + qoff);
#pragma unroll
            for (int jp = 0; jp < 4; ++jp) {
                uint32_t kb[4], kbl[4];
                uint32_t off = (uint32_t)(((rB + 16 * jp) * AST + cF + 16 * kk) * 2);
                ldsm4(kb, aKh + off);
                ldsm4(kbl, aKl + off);
                mma_bf16(sa[2 * jp],     qh, kb[0],  kb[2]);
                mma_bf16(sa[2 * jp],     qh, kbl[0], kbl[2]);
                mma_bf16(sa[2 * jp],     ql, kb[0],  kb[2]);
                mma_bf16(sa[2 * jp + 1], qh, kb[1],  kb[3]);
                mma_bf16(sa[2 * jp + 1], qh, kbl[1], kbl[3]);
                mma_bf16(sa[2 * jp + 1], ql, kb[1],  kb[3]);
            }
        }

        // ---- causal mask on diagonal tile ----
        if (st == qt) {
            int rloc = 16 * w + (lane >> 2);
#pragma unroll
            for (int j = 0; j < 8; ++j) {
                int c = 8 * j + 2 * (lane & 3);
                if (c > rloc)         sa[j][0] = -1e30f;
                if (c + 1 > rloc)     sa[j][1] = -1e30f;
                if (c > rloc + 8)     sa[j][2] = -1e30f;
                if (c + 1 > rloc + 8) sa[j][3] = -1e30f;
            }
        }

        // ---- online softmax ----
        float rmax0 = -1e30f, rmax1 = -1e30f;
#pragma unroll
        for (int j = 0; j < 8; ++j) {
            rmax0 = fmaxf(rmax0, fmaxf(sa[j][0], sa[j][1]));
            rmax1 = fmaxf(rmax1, fmaxf(sa[j][2], sa[j][3]));
        }
#pragma unroll
        for (int off = 1; off < 4; off <<= 1) {
            rmax0 = fmaxf(rmax0, __shfl_xor_sync(0xffffffffu, rmax0, off));
            rmax1 = fmaxf(rmax1, __shfl_xor_sync(0xffffffffu, rmax1, off));
        }
        float mn0 = fmaxf(m0, SCALE * rmax0);
        float mn1 = fmaxf(m1, SCALE * rmax1);
        float al0 = __expf(m0 - mn0);
        float al1 = __expf(m1 - mn1);

        uint32_t pa[4][4], pl[4][4];
        float rs0 = 0.0f, rs1 = 0.0f;
#pragma unroll
        for (int j = 0; j < 8; ++j) {
            float p0 = __expf(fmaf(SCALE, sa[j][0], -mn0));
            float p1 = __expf(fmaf(SCALE, sa[j][1], -mn0));
            float p2 = __expf(fmaf(SCALE, sa[j][2], -mn1));
            float p3 = __expf(fmaf(SCALE, sa[j][3], -mn1));
            rs0 += p0 + p1;
            rs1 += p2 + p3;
            uint32_t h01, l01, h23, l23;
            cvt_hilo(p0, p1, h01, l01);
            cvt_hilo(p2, p3, h23, l23);
            pa[j >> 1][(j & 1) ? 2 : 0] = h01;
            pa[j >> 1][(j & 1) ? 3 : 1] = h23;
            pl[j >> 1][(j & 1) ? 2 : 0] = l01;
            pl[j >> 1][(j & 1) ? 3 : 1] = l23;
        }
#pragma unroll
        for (int off = 1; off < 4; off <<= 1) {
            rs0 += __shfl_xor_sync(0xffffffffu, rs0, off);
            rs1 += __shfl_xor_sync(0xffffffffu, rs1, off);
        }
        l0 = l0 * al0 + rs0;
        l1 = l1 * al1 + rs1;
        m0 = mn0;
        m1 = mn1;
#pragma unroll
        for (int j = 0; j < 8; ++j) {
            oac[j][0] *= al0;
            oac[j][1] *= al0;
            oac[j][2] *= al1;
            oac[j][3] *= al1;
        }

        // ---- O += P V (3-term) ----
#pragma unroll
        for (int ks = 0; ks < 4; ++ks) {
#pragma unroll
            for (int jp = 0; jp < 4; ++jp) {
                uint32_t vh[4], vl[4];
                int row = 16 * ks + (lane & 7) + ((lane >> 3) & 1) * 8;
                int col = 16 * jp + ((lane >> 4) << 3);
                uint32_t off = (uint32_t)((row * AST + col) * 2);
                ldsm4t(vh, aVh + off);
                ldsm4t(vl, aVl + off);
                mma_bf16(oac[2 * jp],     pa[ks], vh[0], vh[1]);
                mma_bf16(oac[2 * jp],     pl[ks], vh[0], vh[1]);
                mma_bf16(oac[2 * jp],     pa[ks], vl[0], vl[1]);
                mma_bf16(oac[2 * jp + 1], pa[ks], vh[2], vh[3]);
                mma_bf16(oac[2 * jp + 1], pl[ks], vh[2], vh[3]);
                mma_bf16(oac[2 * jp + 1], pa[ks], vl[2], vl[3]);
            }
        }
    }

    // Epilogue: normalize, hi/lo split, store bf16 for out-projection
    float inv0 = 1.0f / l0;
    float inv1 = 1.0f / l1;
    int row = qt * 64 + 16 * w + (lane >> 2);
    size_t ob = (size_t)row * DMODEL + h * DHEAD;
#pragma unroll
    for (int j = 0; j < 8; ++j) {
        int col = 8 * j + 2 * (lane & 3);
        uint32_t hh, ll;
        cvt_hilo(oac[j][0] * inv0, oac[j][1] * inv0, hh, ll);
        *reinterpret_cast<uint32_t*>(g_ah + ob + col) = hh;
        *reinterpret_cast<uint32_t*>(g_al + ob + col) = ll;
        cvt_hilo(oac[j][2] * inv1, oac[j][3] * inv1, hh, ll);
        *reinterpret_cast<uint32_t*>(g_ah + ob + (size_t)8 * DMODEL + col) = hh;
        *reinterpret_cast<uint32_t*>(g_al + ob + (size_t)8 * DMODEL + col) = ll;
    }
}

// ---------------------------------------------------------------------------
extern "C" void kernel_launch(void* const* d_in, const int* in_sizes, int n_in,
                              void* d_out, int out_size) {
    const float* x  = (const float*)d_in[0];
    const float* Wq = (const float*)d_in[1];
    const float* Wk = (const float*)d_in[2];
    const float* Wv = (const float*)d_in[3];
    const float* Wo = (const float*)d_in[4];
    const float* rc = (const float*)d_in[5];
    const float* rs = (const float*)d_in[6];
    float* out = (float*)d_out;

    static bool attrs_set = false;
    if (!attrs_set) {
        cudaFuncSetAttribute(attn_hmma, cudaFuncAttributeMaxDynamicSharedMemorySize,
                             ATTN_SMEM_BYTES);
        cudaFuncSetAttribute(qkv_hmma, cudaFuncAttributeMaxDynamicSharedMemorySize,
                             GEMM_SMEM_BYTES);
        cudaFuncSetAttribute(out_hmma, cudaFuncAttributeMaxDynamicSharedMemorySize,
                             GEMM_SMEM_BYTES);
        attrs_set = true;
    }

    __nv_bfloat16 *d_xh, *d_xl, *d_wh, *d_wl, *d_woh, *d_wol;
    __nv_bfloat16 *d_qh, *d_ql, *d_kh, *d_kl;
    float *d_q, *d_k;
    cudaGetSymbolAddress((void**)&d_xh, g_xh);
    cudaGetSymbolAddress((void**)&d_xl, g_xl);
    cudaGetSymbolAddress((void**)&d_wh, g_wh);
    cudaGetSymbolAddress((void**)&d_wl, g_wl);
    cudaGetSymbolAddress((void**)&d_woh, g_woh);
    cudaGetSymbolAddress((void**)&d_wol, g_wol);
    cudaGetSymbolAddress((void**)&d_qh, g_qh);
    cudaGetSymbolAddress((void**)&d_ql, g_ql);
    cudaGetSymbolAddress((void**)&d_kh, g_kh);
    cudaGetSymbolAddress((void**)&d_kl, g_kl);
    cudaGetSymbolAddress((void**)&d_q, g_q);
    cudaGetSymbolAddress((void**)&d_k, g_k);

    // 0) Pre-convert inputs to hi/lo bf16 (once per launch)
    {
        int n;
        n = TSEQ * DMODEL;          // x
        cvt_kernel<<<n / 1024, 256>>>(x, d_xh, d_xl, n);
        n = 2048 * DMODEL;          // Wq -> rows [0, 2048)
        cvt_kernel<<<n / 1024, 256>>>(Wq, d_wh, d_wl, n);
        n = 512 * DMODEL;           // Wk -> rows [2048, 2560)
        cvt_kernel<<<n / 1024, 256>>>(Wk, d_wh + (size_t)2048 * DMODEL,
                                      d_wl + (size_t)2048 * DMODEL, n);
        n = 512 * DMODEL;           // Wv -> rows [2560, 3072)
        cvt_kernel<<<n / 1024, 256>>>(Wv, d_wh + (size_t)2560 * DMODEL,
                                      d_wl + (size_t)2560 * DMODEL, n);
        n = DMODEL * DMODEL;        // Wo
        cvt_kernel<<<n / 1024, 256>>>(Wo, d_woh, d_wol, n);
    }

    // 1) Fused QKV projection (bf16 hi/lo, 3-term HMMA, cp.async pipeline)
    qkv_hmma<<<dim3(24, 16), 256, GEMM_SMEM_BYTES>>>();

    // 2) RoPE + hi/lo conversion for Q and K
    {
        int totq = TSEQ * HQ * 32;
        rope_cvt_kernel<<<(totq + 255) / 256, 256>>>(d_q, rc, rs, d_qh, d_ql, HQ);
        int totk = TSEQ * HKV * 32;
        rope_cvt_kernel<<<(totk + 255) / 256, 256>>>(d_k, rc, rs, d_kh, d_kl, HKV);
    }

    // 3) Causal GQA attention (HMMA, bf16 direct)
    attn_hmma<<<dim3(TSEQ / 64, HQ), 128, ATTN_SMEM_BYTES>>>();

    // 4) Output projection
    out_hmma<<<dim3(16, 16), 256, GEMM_SMEM_BYTES>>>(out);
}

// round 6
// speedup vs baseline: 1.0263x; 1.0263x over previous
#include <cuda_runtime.h>
#include <cuda_bf16.h>
#include <math.h>
#include <cstdint>

// Problem constants
#define TSEQ 2048
#define DMODEL 2048
#define HQ 32
#define HKV 8
#define DHEAD 64
#define DKV (HKV * DHEAD)   // 512

// ---------------------------------------------------------------------------
// Device-global scratch (allocation-free rule). All bf16 arrays 16B-aligned.
// ---------------------------------------------------------------------------
__device__ float g_q[TSEQ * DMODEL];                       // fp32 Q pre-rope
__device__ float g_k[TSEQ * DKV];                          // fp32 K pre-rope
__device__ __align__(16) __nv_bfloat16 g_xh[TSEQ * DMODEL], g_xl[TSEQ * DMODEL];
__device__ __align__(16) __nv_bfloat16 g_wh[3072 * DMODEL], g_wl[3072 * DMODEL];
__device__ __align__(16) __nv_bfloat16 g_woh[DMODEL * DMODEL], g_wol[DMODEL * DMODEL];
__device__ __align__(16) __nv_bfloat16 g_qh[TSEQ * DMODEL], g_ql[TSEQ * DMODEL];
__device__ __align__(16) __nv_bfloat16 g_kh[TSEQ * DKV], g_kl[TSEQ * DKV];
__device__ __align__(16) __nv_bfloat16 g_vh[TSEQ * DKV], g_vl[TSEQ * DKV];
__device__ __align__(16) __nv_bfloat16 g_ah[TSEQ * DMODEL], g_al[TSEQ * DMODEL];

// ===========================================================================
// Warp-MMA / async-copy helpers (sm_80+ baseline; no sm_103a-only features)
// ===========================================================================
__device__ __forceinline__ uint32_t smem_u32(const void* p) {
    uint32_t a;
    asm("{ .reg .u64 t; cvta.to.shared.u64 t, %1; cvt.u32.u64 %0, t; }"
        : "=r"(a) : "l"(p));
    return a;
}
__device__ __forceinline__ void ldsm4(uint32_t* r, uint32_t a) {
    asm volatile("ldmatrix.sync.aligned.m8n8.x4.shared.b16 {%0,%1,%2,%3}, [%4];"
                 : "=r"(r[0]), "=r"(r[1]), "=r"(r[2]), "=r"(r[3]) : "r"(a));
}
__device__ __forceinline__ void ldsm4t(uint32_t* r, uint32_t a) {
    asm volatile("ldmatrix.sync.aligned.m8n8.x4.trans.shared.b16 {%0,%1,%2,%3}, [%4];"
                 : "=r"(r[0]), "=r"(r[1]), "=r"(r[2]), "=r"(r[3]) : "r"(a));
}
__device__ __forceinline__ void mma_bf16(float* c, const uint32_t* a,
                                         uint32_t b0, uint32_t b1) {
    asm volatile(
        "mma.sync.aligned.m16n8k16.row.col.f32.bf16.bf16.f32 "
        "{%0,%1,%2,%3}, {%4,%5,%6,%7}, {%8,%9}, {%0,%1,%2,%3};"
        : "+f"(c[0]), "+f"(c[1]), "+f"(c[2]), "+f"(c[3])
        : "r"(a[0]), "r"(a[1]), "r"(a[2]), "r"(a[3]), "r"(b0), "r"(b1));
}
__device__ __forceinline__ void cp_async16(uint32_t dst, const void* src) {
    asm volatile("cp.async.cg.shared.global [%0], [%1], 16;" :: "r"(dst), "l"(src));
}
#define CP_COMMIT() asm volatile("cp.async.commit_group;" ::: "memory")
#define CP_WAIT(N)  asm volatile("cp.async.wait_group %0;" :: "n"(N) : "memory")

__device__ __forceinline__ uint32_t u32of(__nv_bfloat162 h) {
    return *reinterpret_cast<uint32_t*>(&h);
}
__device__ __forceinline__ void cvt_hilo(float x, float y, uint32_t& hi, uint32_t& lo) {
    __nv_bfloat162 h = __floats2bfloat162_rn(x, y);
    float2 hf = __bfloat1622float2(h);
    __nv_bfloat162 l = __floats2bfloat162_rn(x - hf.x, y - hf.y);
    hi = u32of(h);
    lo = u32of(l);
}

// ---------------------------------------------------------------------------
// fp32 -> hi/lo bf16 conversion kernel (vectorized by 4)
// ---------------------------------------------------------------------------
__global__ void cvt_kernel(const float* __restrict__ src,
                           __nv_bfloat16* __restrict__ dh,
                           __nv_bfloat16* __restrict__ dl, int n) {
    int i = (blockIdx.x * blockDim.x + threadIdx.x) * 4;
    if (i >= n) return;
    float4 f = *reinterpret_cast<const float4*>(src + i);
    uint32_t h0, l0, h1, l1;
    cvt_hilo(f.x, f.y, h0, l0);
    cvt_hilo(f.z, f.w, h1, l1);
    *reinterpret_cast<uint32_t*>(dh + i)     = h0;
    *reinterpret_cast<uint32_t*>(dh + i + 2) = h1;
    *reinterpret_cast<uint32_t*>(dl + i)     = l0;
    *reinterpret_cast<uint32_t*>(dl + i + 2) = l1;
}

// ---------------------------------------------------------------------------
// RoPE: fp32 in -> rotated hi/lo bf16 out
// ---------------------------------------------------------------------------
__global__ void rope_cvt_kernel(const float* __restrict__ src,
                                const float* __restrict__ cosb,
                                const float* __restrict__ sinb,
                                __nv_bfloat16* __restrict__ dh,
                                __nv_bfloat16* __restrict__ dl, int H) {
    int idx = blockIdx.x * blockDim.x + threadIdx.x;
    int total = TSEQ * H * 32;
    if (idx >= total) return;
    int i = idx & 31;
    int h = (idx >> 5) % H;
    int t = idx / (32 * H);
    float c = cosb[t * 32 + i];
    float s = sinb[t * 32 + i];
    size_t off = ((size_t)t * H + h) * DHEAD + 2 * i;
    float x0 = src[off], x1 = src[off + 1];
    float o0 = x0 * c - x1 * s;
    float o1 = x0 * s + x1 * c;
    uint32_t hh, ll;
    cvt_hilo(o0, o1, hh, ll);
    *reinterpret_cast<uint32_t*>(dh + off) = hh;
    *reinterpret_cast<uint32_t*>(dl + off) = ll;
}

// ===========================================================================
// Projection GEMM (bf16 hi/lo inputs, 3-term HMMA, cp.async 2-stage pipeline,
// term-outermost MMA ordering for accumulator independence).
// C[128,128] tile of A[M,2048] · B[N,2048]^T. 256 thr = 8 warps, 64x32/warp.
// ===========================================================================
#define GST 40                       // smem row stride in halves (80B)
#define TILE_H (128 * GST)           // halves per tile buffer (5120)
#define STAGE_H (4 * TILE_H)         // Ah,Al,Bh,Bl per stage
constexpr int GEMM_SMEM_BYTES = 2 * STAGE_H * 2;   // 81920

__device__ __forceinline__ void gemm_loads(uint32_t sb, int stage,
                                           const __nv_bfloat16* Ah,
                                           const __nv_bfloat16* Al,
                                           const __nv_bfloat16* Bh,
                                           const __nv_bfloat16* Bl,
                                           int k0, int tid) {
    const __nv_bfloat16* bases[4] = {Ah, Al, Bh, Bl};
    uint32_t dbase = sb + (uint32_t)stage * STAGE_H * 2;
#pragma unroll
    for (int t = 0; t < 4; ++t) {
#pragma unroll
        for (int it = 0; it < 2; ++it) {
            int slot = tid + it * 256;      // 512 slots: 128 rows x 4 chunks
            int row = slot >> 2;
            int q = slot & 3;
            const void* src = bases[t] + (size_t)row * 2048 + k0 + q * 8;
            uint32_t dst = dbase + (uint32_t)(t * TILE_H + row * GST + q * 8) * 2;
            cp_async16(dst, src);
        }
    }
}

__device__ void gemm_body(const __nv_bfloat16* __restrict__ Ah,
                          const __nv_bfloat16* __restrict__ Al,
                          const __nv_bfloat16* __restrict__ Bh,
                          const __nv_bfloat16* __restrict__ Bl,
                          float* Cf, __nv_bfloat16* Cvh, __nv_bfloat16* Cvl,
                          int ldc, int vout) {
    extern __shared__ uint16_t sm16[];
    uint32_t sb = smem_u32(sm16);
    int tid = threadIdx.x;
    int lane = tid & 31;
    int wid = tid >> 5;
    int m0 = (wid & 1) * 64;
    int n0 = (wid >> 1) * 32;

    float acc[4][4][4];
#pragma unroll
    for (int i = 0; i < 4; ++i)
#pragma unroll
        for (int j = 0; j < 4; ++j)
#pragma unroll
            for (int q = 0; q < 4; ++q) acc[i][j][q] = 0.0f;

    gemm_loads(sb, 0, Ah, Al, Bh, Bl, 0, tid);
    CP_COMMIT();

    for (int i = 0; i < 64; ++i) {
        int s = i & 1;
        if (i < 63) {
            gemm_loads(sb, s ^ 1, Ah, Al, Bh, Bl, (i + 1) * 32, tid);
            CP_COMMIT();
            CP_WAIT(1);
        } else {
            CP_WAIT(0);
        }
        __syncthreads();

        uint32_t aAh = sb + (uint32_t)s * STAGE_H * 2;
        uint32_t aAl = aAh + TILE_H * 2;
        uint32_t aBh = aAl + TILE_H * 2;
        uint32_t aBl = aBh + TILE_H * 2;

#pragma unroll
        for (int kk = 0; kk < 2; ++kk) {
            uint32_t ah[4][4], al[4][4];
            int rA = m0 + (lane & 15);
            int cA = kk * 16 + ((lane >> 4) << 3);
#pragma unroll
            for (int i2 = 0; i2 < 4; ++i2) {
                uint32_t off = (uint32_t)(((rA + 16 * i2) * GST + cA) * 2);
                ldsm4(ah[i2], aAh + off);
                ldsm4(al[i2], aAl + off);
            }
            uint32_t bh[2][4], bl[2][4];
            int rB = n0 + (lane & 7) + ((lane >> 3) & 1) * 8;
            int cB = kk * 16 + ((lane >> 4) << 3);
#pragma unroll
            for (int jp = 0; jp < 2; ++jp) {
                uint32_t off = (uint32_t)(((rB + 16 * jp) * GST + cB) * 2);
                ldsm4(bh[jp], aBh + off);
                ldsm4(bl[jp], aBl + off);
            }
            // term hi·hi: 16 independent-accumulator MMAs
#pragma unroll
            for (int i2 = 0; i2 < 4; ++i2)
#pragma unroll
                for (int jp = 0; jp < 2; ++jp) {
                    mma_bf16(acc[i2][2 * jp],     ah[i2], bh[jp][0], bh[jp][2]);
                    mma_bf16(acc[i2][2 * jp + 1], ah[i2], bh[jp][1], bh[jp][3]);
                }
            // term hi·lo
#pragma unroll
            for (int i2 = 0; i2 < 4; ++i2)
#pragma unroll
                for (int jp = 0; jp < 2; ++jp) {
                    mma_bf16(acc[i2][2 * jp],     ah[i2], bl[jp][0], bl[jp][2]);
                    mma_bf16(acc[i2][2 * jp + 1], ah[i2], bl[jp][1], bl[jp][3]);
                }
            // term lo·hi
#pragma unroll
            for (int i2 = 0; i2 < 4; ++i2)
#pragma unroll
                for (int jp = 0; jp < 2; ++jp) {
                    mma_bf16(acc[i2][2 * jp],     al[i2], bh[jp][0], bh[jp][2]);
                    mma_bf16(acc[i2][2 * jp + 1], al[i2], bh[jp][1], bh[jp][3]);
                }
        }
        __syncthreads();
    }

    int r = m0 + (lane >> 2);
    int cq = 2 * (lane & 3);
    if (!vout) {
#pragma unroll
        for (int i = 0; i < 4; ++i)
#pragma unroll
            for (int j = 0; j < 4; ++j) {
                int row = r + 16 * i;
                int col = n0 + 8 * j + cq;
                *reinterpret_cast<float2*>(Cf + (size_t)row * ldc + col) =
                    make_float2(acc[i][j][0], acc[i][j][1]);
                *reinterpret_cast<float2*>(Cf + (size_t)(row + 8) * ldc + col) =
                    make_float2(acc[i][j][2], acc[i][j][3]);
            }
    } else {
#pragma unroll
        for (int i = 0; i < 4; ++i)
#pragma unroll
            for (int j = 0; j < 4; ++j) {
                int row = r + 16 * i;
                int col = n0 + 8 * j + cq;
                uint32_t hh, ll;
                cvt_hilo(acc[i][j][0], acc[i][j][1], hh, ll);
                *reinterpret_cast<uint32_t*>(Cvh + (size_t)row * ldc + col) = hh;
                *reinterpret_cast<uint32_t*>(Cvl + (size_t)row * ldc + col) = ll;
                cvt_hilo(acc[i][j][2], acc[i][j][3], hh, ll);
                *reinterpret_cast<uint32_t*>(Cvh + (size_t)(row + 8) * ldc + col) = hh;
                *reinterpret_cast<uint32_t*>(Cvl + (size_t)(row + 8) * ldc + col) = ll;
            }
    }
}

// QKV projection: N = 2048 (Q) + 512 (K) + 512 (V, direct hi/lo bf16 out)
__global__ __launch_bounds__(256) void qkv_hmma() {
    int bm = blockIdx.y * 128;
    int bn = blockIdx.x * 128;
    const __nv_bfloat16* Ah = g_xh + (size_t)bm * DMODEL;
    const __nv_bfloat16* Al = g_xl + (size_t)bm * DMODEL;
    const __nv_bfloat16* Bh = g_wh + (size_t)bn * DMODEL;
    const __nv_bfloat16* Bl = g_wl + (size_t)bn * DMODEL;
    if (bn < 2048) {
        gemm_body(Ah, Al, Bh, Bl, g_q + (size_t)bm * DMODEL + bn,
                  nullptr, nullptr, DMODEL, 0);
    } else if (bn < 2560) {
        gemm_body(Ah, Al, Bh, Bl, g_k + (size_t)bm * DKV + (bn - 2048),
                  nullptr, nullptr, DKV, 0);
    } else {
        gemm_body(Ah, Al, Bh, Bl, nullptr,
                  g_vh + (size_t)bm * DKV + (bn - 2560),
                  g_vl + (size_t)bm * DKV + (bn - 2560), DKV, 1);
    }
}

__global__ __launch_bounds__(256) void out_hmma(float* __restrict__ out) {
    int bm = blockIdx.y * 128;
    int bn = blockIdx.x * 128;
    gemm_body(g_ah + (size_t)bm * DMODEL, g_al + (size_t)bm * DMODEL,
              g_woh + (size_t)bn * DMODEL, g_wol + (size_t)bn * DMODEL,
              out + (size_t)bm * DMODEL + bn, nullptr, nullptr, DMODEL, 0);
}

// ===========================================================================
// FA2-style causal GQA attention, bf16 hi/lo, term-outermost MMA ordering,
// triangle-balanced: grid (16, HQ); block does qt=bi then qt=31-bi (33 tiles).
// 128 threads (4 warps), 16 q-rows/warp, BS=64.
// ===========================================================================
#define AST 72   // smem row stride in halves (144B)
constexpr int ATTN_SMEM_BYTES = 6 * 64 * AST * 2;   // 55296

__global__ __launch_bounds__(128, 3) void attn_hmma() {
    extern __shared__ uint16_t sm16[];
    uint16_t* sQh = sm16;
    uint16_t* sQl = sQh + 64 * AST;
    uint16_t* sKh = sQl + 64 * AST;
    uint16_t* sKl = sKh + 64 * AST;
    uint16_t* sVh = sKl + 64 * AST;
    uint16_t* sVl = sVh + 64 * AST;
    uint32_t aQh = smem_u32(sQh), aQl = smem_u32(sQl);
    uint32_t aKh = smem_u32(sKh), aKl = smem_u32(sKl);
    uint32_t aVh = smem_u32(sVh), aVl = smem_u32(sVl);

    int tid = threadIdx.x;
    int lane = tid & 31;
    int w = tid >> 5;
    int h = blockIdx.y;
    int kvh = h >> 2;
    const float SCALE = 0.125f;

    for (int pass = 0; pass < 2; ++pass) {
        int qt = pass == 0 ? (int)blockIdx.x : 31 - (int)blockIdx.x;

        __syncthreads();   // prior pass fully done before overwriting sQ
        // Load Q tile (bf16 hi/lo, 64 x 64)
        {
            const __nv_bfloat16* qsrc[2] = {g_qh, g_ql};
            uint16_t* qdst[2] = {sQh, sQl};
#pragma unroll
            for (int it = 0; it < 8; ++it) {
                int slot = tid + it * 128;       // 1024 slots
                int t = slot >> 9;
                int r = (slot >> 3) & 63;
                int q = slot & 7;
                const __nv_bfloat16* src =
                    qsrc[t] + (size_t)(qt * 64 + r) * DMODEL + h * DHEAD + q * 8;
                *reinterpret_cast<uint4*>(qdst[t] + r * AST + q * 8) =
                    *reinterpret_cast<const uint4*>(src);
            }
        }

        float m0 = -1e30f, m1 = -1e30f, l0 = 0.0f, l1 = 0.0f;
        float oac[8][4];
#pragma unroll
        for (int j = 0; j < 8; ++j)
#pragma unroll
            for (int q = 0; q < 4; ++q) oac[j][q] = 0.0f;

        for (int st = 0; st <= qt; ++st) {
            __syncthreads();    // previous PV (and Q store) complete
            // Load K/V tiles (bf16 hi/lo, 64 x 64 each)
            {
                const __nv_bfloat16* srcs[4] = {g_kh, g_kl, g_vh, g_vl};
                uint16_t* dsts[4] = {sKh, sKl, sVh, sVl};
#pragma unroll
                for (int it = 0; it < 16; ++it) {
                    int slot = tid + it * 128;   // 2048 slots
                    int t = slot >> 9;
                    int r = (slot >> 3) & 63;
                    int q = slot & 7;
                    const __nv_bfloat16* src =
                        srcs[t] + (size_t)(st * 64 + r) * DKV + kvh * DHEAD + q * 8;
                    *reinterpret_cast<uint4*>(dsts[t] + r * AST + q * 8) =
                        *reinterpret_cast<const uint4*>(src);
                }
            }
            __syncthreads();

            // ---- S = Q K^T (3-term hi/lo, term-outermost) ----
            float sa[8][4];
#pragma unroll
            for (int j = 0; j < 8; ++j)
#pragma unroll
                for (int q = 0; q < 4; ++q) sa[j][q] = 0.0f;

            int rQ = 16 * w + (lane & 15);
            int rB = (lane & 7) + ((lane >> 3) & 1) * 8;
            int cF = ((lane >> 4) << 3);
#pragma unroll
            for (int kk = 0; kk < 4; ++kk) {
                uint32_t qh[4], ql[4];
                uint32_t qoff = (uint32_t)((rQ * AST + cF + 16 * kk) * 2);
                ldsm4(qh, aQh + qoff);
                ldsm4(ql, aQl + qoff);
                uint32_t kb[4][4], kbl[4][4];
#pragma unroll
                for (int jp = 0; jp < 4; ++jp) {
                    uint32_t off = (uint32_t)(((rB + 16 * jp) * AST + cF + 16 * kk) * 2);
                    ldsm4(kb[jp], aKh + off);
                    ldsm4(kbl[jp], aKl + off);
                }
                // term hi·hi: 8 independent MMAs
#pragma unroll
                for (int jp = 0; jp < 4; ++jp) {
                    mma_bf16(sa[2 * jp],     qh, kb[jp][0], kb[jp][2]);
                    mma_bf16(sa[2 * jp + 1], qh, kb[jp][1], kb[jp][3]);
                }
                // term hi·lo
#pragma unroll
                for (int jp = 0; jp < 4; ++jp) {
                    mma_bf16(sa[2 * jp],     qh, kbl[jp][0], kbl[jp][2]);
                    mma_bf16(sa[2 * jp + 1], qh, kbl[jp][1], kbl[jp][3]);
                }
                // term lo·hi
#pragma unroll
                for (int jp = 0; jp < 4; ++jp) {
                    mma_bf16(sa[2 * jp],     ql, kb[jp][0], kb[jp][2]);
                    mma_bf16(sa[2 * jp + 1], ql, kb[jp][1], kb[jp][3]);
                }
            }

            // ---- causal mask on diagonal tile ----
            if (st == qt) {
                int rloc = 16 * w + (lane >> 2);
#pragma unroll
                for (int j = 0; j < 8; ++j) {
                    int c = 8 * j + 2 * (lane & 3);
                    if (c > rloc)         sa[j][0] = -1e30f;
                    if (c + 1 > rloc)     sa[j][1] = -1e30f;
                    if (c > rloc + 8)     sa[j][2] = -1e30f;
                    if (c + 1 > rloc + 8) sa[j][3] = -1e30f;
                }
            }

            // ---- online softmax ----
            float rmax0 = -1e30f, rmax1 = -1e30f;
#pragma unroll
            for (int j = 0; j < 8; ++j) {
                rmax0 = fmaxf(rmax0, fmaxf(sa[j][0], sa[j][1]));
                rmax1 = fmaxf(rmax1, fmaxf(sa[j][2], sa[j][3]));
            }
#pragma unroll
            for (int off = 1; off < 4; off <<= 1) {
                rmax0 = fmaxf(rmax0, __shfl_xor_sync(0xffffffffu, rmax0, off));
                rmax1 = fmaxf(rmax1, __shfl_xor_sync(0xffffffffu, rmax1, off));
            }
            float mn0 = fmaxf(m0, SCALE * rmax0);
            float mn1 = fmaxf(m1, SCALE * rmax1);
            float al0 = __expf(m0 - mn0);
            float al1 = __expf(m1 - mn1);

            uint32_t pa[4][4], pl[4][4];
            float rs0 = 0.0f, rs1 = 0.0f;
#pragma unroll
            for (int j = 0; j < 8; ++j) {
                float p0 = __expf(fmaf(SCALE, sa[j][0], -mn0));
                float p1 = __expf(fmaf(SCALE, sa[j][1], -mn0));
                float p2 = __expf(fmaf(SCALE, sa[j][2], -mn1));
                float p3 = __expf(fmaf(SCALE, sa[j][3], -mn1));
                rs0 += p0 + p1;
                rs1 += p2 + p3;
                uint32_t h01, l01, h23, l23;
                cvt_hilo(p0, p1, h01, l01);
                cvt_hilo(p2, p3, h23, l23);
                pa[j >> 1][(j & 1) ? 2 : 0] = h01;
                pa[j >> 1][(j & 1) ? 3 : 1] = h23;
                pl[j >> 1][(j & 1) ? 2 : 0] = l01;
                pl[j >> 1][(j & 1) ? 3 : 1] = l23;
            }
#pragma unroll
            for (int off = 1; off < 4; off <<= 1) {
                rs0 += __shfl_xor_sync(0xffffffffu, rs0, off);
                rs1 += __shfl_xor_sync(0xffffffffu, rs1, off);
            }
            l0 = l0 * al0 + rs0;
            l1 = l1 * al1 + rs1;
            m0 = mn0;
            m1 = mn1;
#pragma unroll
            for (int j = 0; j < 8; ++j) {
                oac[j][0] *= al0;
                oac[j][1] *= al0;
                oac[j][2] *= al1;
                oac[j][3] *= al1;
            }

            // ---- O += P V (3-term, term-outermost per ks) ----
#pragma unroll
            for (int ks = 0; ks < 4; ++ks) {
                uint32_t vh[4][4], vl[4][4];
                int row = 16 * ks + (lane & 7) + ((lane >> 3) & 1) * 8;
#pragma unroll
                for (int jp = 0; jp < 4; ++jp) {
                    int col = 16 * jp + ((lane >> 4) << 3);
                    uint32_t off = (uint32_t)((row * AST + col) * 2);
                    ldsm4t(vh[jp], aVh + off);
                    ldsm4t(vl[jp], aVl + off);
                }
                // term Phi·Vhi: 8 independent MMAs
#pragma unroll
                for (int jp = 0; jp < 4; ++jp) {
                    mma_bf16(oac[2 * jp],     pa[ks], vh[jp][0], vh[jp][1]);
                    mma_bf16(oac[2 * jp + 1], pa[ks], vh[jp][2], vh[jp][3]);
                }
                // term Plo·Vhi
#pragma unroll
                for (int jp = 0; jp < 4; ++jp) {
                    mma_bf16(oac[2 * jp],     pl[ks], vh[jp][0], vh[jp][1]);
                    mma_bf16(oac[2 * jp + 1], pl[ks], vh[jp][2], vh[jp][3]);
                }
                // term Phi·Vlo
#pragma unroll
                for (int jp = 0; jp < 4; ++jp) {
                    mma_bf16(oac[2 * jp],     pa[ks], vl[jp][0], vl[jp][1]);
                    mma_bf16(oac[2 * jp + 1], pa[ks], vl[jp][2], vl[jp][3]);
                }
            }
        }

        // Epilogue: normalize, hi/lo split, store bf16 for out-projection
        float inv0 = 1.0f / l0;
        float inv1 = 1.0f / l1;
        int row = qt * 64 + 16 * w + (lane >> 2);
        size_t ob = (size_t)row * DMODEL + h * DHEAD;
#pragma unroll
        for (int j = 0; j < 8; ++j) {
            int col = 8 * j + 2 * (lane & 3);
            uint32_t hh, ll;
            cvt_hilo(oac[j][0] * inv0, oac[j][1] * inv0, hh, ll);
            *reinterpret_cast<uint32_t*>(g_ah + ob + col) = hh;
            *reinterpret_cast<uint32_t*>(g_al + ob + col) = ll;
            cvt_hilo(oac[j][2] * inv1, oac[j][3] * inv1, hh, ll);
            *reinterpret_cast<uint32_t*>(g_ah + ob + (size_t)8 * DMODEL + col) = hh;
            *reinterpret_cast<uint32_t*>(g_al + ob + (size_t)8 * DMODEL + col) = ll;
        }
    }
}

// ---------------------------------------------------------------------------
extern "C" void kernel_launch(void* const* d_in, const int* in_sizes, int n_in,
                              void* d_out, int out_size) {
    const float* x  = (const float*)d_in[0];
    const float* Wq = (const float*)d_in[1];
    const float* Wk = (const float*)d_in[2];
    const float* Wv = (const float*)d_in[3];
    const float* Wo = (const float*)d_in[4];
    const float* rc = (const float*)d_in[5];
    const float* rs = (const float*)d_in[6];
    float* out = (float*)d_out;

    static bool attrs_set = false;
    if (!attrs_set) {
        cudaFuncSetAttribute(attn_hmma, cudaFuncAttributeMaxDynamicSharedMemorySize,
                             ATTN_SMEM_BYTES);
        cudaFuncSetAttribute(qkv_hmma, cudaFuncAttributeMaxDynamicSharedMemorySize,
                             GEMM_SMEM_BYTES);
        cudaFuncSetAttribute(out_hmma, cudaFuncAttributeMaxDynamicSharedMemorySize,
                             GEMM_SMEM_BYTES);
        attrs_set = true;
    }

    __nv_bfloat16 *d_xh, *d_xl, *d_wh, *d_wl, *d_woh, *d_wol;
    __nv_bfloat16 *d_qh, *d_ql, *d_kh, *d_kl;
    float *d_q, *d_k;
    cudaGetSymbolAddress((void**)&d_xh, g_xh);
    cudaGetSymbolAddress((void**)&d_xl, g_xl);
    cudaGetSymbolAddress((void**)&d_wh, g_wh);
    cudaGetSymbolAddress((void**)&d_wl, g_wl);
    cudaGetSymbolAddress((void**)&d_woh, g_woh);
    cudaGetSymbolAddress((void**)&d_wol, g_wol);
    cudaGetSymbolAddress((void**)&d_qh, g_qh);
    cudaGetSymbolAddress((void**)&d_ql, g_ql);
    cudaGetSymbolAddress((void**)&d_kh, g_kh);
    cudaGetSymbolAddress((void**)&d_kl, g_kl);
    cudaGetSymbolAddress((void**)&d_q, g_q);
    cudaGetSymbolAddress((void**)&d_k, g_k);

    // 0) Pre-convert inputs to hi/lo bf16 (once per launch)
    {
        int n;
        n = TSEQ * DMODEL;          // x
        cvt_kernel<<<n / 1024, 256>>>(x, d_xh, d_xl, n);
        n = 2048 * DMODEL;          // Wq -> rows [0, 2048)
        cvt_kernel<<<n / 1024, 256>>>(Wq, d_wh, d_wl, n);
        n = 512 * DMODEL;           // Wk -> rows [2048, 2560)
        cvt_kernel<<<n / 1024, 256>>>(Wk, d_wh + (size_t)2048 * DMODEL,
                                      d_wl + (size_t)2048 * DMODEL, n);
        n = 512 * DMODEL;           // Wv -> rows [2560, 3072)
        cvt_kernel<<<n / 1024, 256>>>(Wv, d_wh + (size_t)2560 * DMODEL,
                                      d_wl + (size_t)2560 * DMODEL, n);
        n = DMODEL * DMODEL;        // Wo
        cvt_kernel<<<n / 1024, 256>>>(Wo, d_woh, d_wol, n);
    }

    // 1) Fused QKV projection (bf16 hi/lo, 3-term HMMA, cp.async pipeline)
    qkv_hmma<<<dim3(24, 16), 256, GEMM_SMEM_BYTES>>>();

    // 2) RoPE + hi/lo conversion for Q and K
    {
        int totq = TSEQ * HQ * 32;
        rope_cvt_kernel<<<(totq + 255) / 256, 256>>>(d_q, rc, rs, d_qh, d_ql, HQ);
        int totk = TSEQ * HKV * 32;
        rope_cvt_kernel<<<(totk + 255) / 256, 256>>>(d_k, rc, rs, d_kh, d_kl, HKV);
    }

    // 3) Causal GQA attention (HMMA, triangle-balanced)
    attn_hmma<<<dim3(16, HQ), 128, ATTN_SMEM_BYTES>>>();

    // 4) Output projection
    out_hmma<<<dim3(16, 16), 256, GEMM_SMEM_BYTES>>>(out);
}

// round 7
// speedup vs baseline: 1.3216x; 1.2877x over previous
#include <cuda_runtime.h>
#include <cuda_fp16.h>
#include <math.h>
#include <cstdint>

// Problem constants
#define TSEQ 2048
#define DMODEL 2048
#define HQ 32
#define HKV 8
#define DHEAD 64
#define DKV (HKV * DHEAD)   // 512

// ---------------------------------------------------------------------------
// Device-global scratch (allocation-free rule). fp16 arrays 16B-aligned.
// ---------------------------------------------------------------------------
__device__ float g_q[TSEQ * DMODEL];                       // fp32 Q pre-rope
__device__ float g_k[TSEQ * DKV];                          // fp32 K pre-rope
__device__ __align__(16) __half g_xh[TSEQ * DMODEL], g_xl[TSEQ * DMODEL];
__device__ __align__(16) __half g_wh[3072 * DMODEL];               // W qkv hi only
__device__ __align__(16) __half g_woh[DMODEL * DMODEL];            // Wo hi only
__device__ __align__(16) __half g_qh[TSEQ * DMODEL], g_ql[TSEQ * DMODEL];
__device__ __align__(16) __half g_kh[TSEQ * DKV], g_kl[TSEQ * DKV];
__device__ __align__(16) __half g_vh[TSEQ * DKV];                  // V hi only
__device__ __align__(16) __half g_ah[TSEQ * DMODEL], g_al[TSEQ * DMODEL];

// ===========================================================================
// Warp-MMA / async-copy helpers (sm_80+ baseline; no sm_103a-only features)
// ===========================================================================
__device__ __forceinline__ uint32_t smem_u32(const void* p) {
    uint32_t a;
    asm("{ .reg .u64 t; cvta.to.shared.u64 t, %1; cvt.u32.u64 %0, t; }"
        : "=r"(a) : "l"(p));
    return a;
}
__device__ __forceinline__ void ldsm4(uint32_t* r, uint32_t a) {
    asm volatile("ldmatrix.sync.aligned.m8n8.x4.shared.b16 {%0,%1,%2,%3}, [%4];"
                 : "=r"(r[0]), "=r"(r[1]), "=r"(r[2]), "=r"(r[3]) : "r"(a));
}
__device__ __forceinline__ void ldsm4t(uint32_t* r, uint32_t a) {
    asm volatile("ldmatrix.sync.aligned.m8n8.x4.trans.shared.b16 {%0,%1,%2,%3}, [%4];"
                 : "=r"(r[0]), "=r"(r[1]), "=r"(r[2]), "=r"(r[3]) : "r"(a));
}
// D += A * B  (m16n8k16, fp16 in, fp32 acc)
__device__ __forceinline__ void mma_f16(float* c, const uint32_t* a,
                                        uint32_t b0, uint32_t b1) {
    asm volatile(
        "mma.sync.aligned.m16n8k16.row.col.f32.f16.f16.f32 "
        "{%0,%1,%2,%3}, {%4,%5,%6,%7}, {%8,%9}, {%0,%1,%2,%3};"
        : "+f"(c[0]), "+f"(c[1]), "+f"(c[2]), "+f"(c[3])
        : "r"(a[0]), "r"(a[1]), "r"(a[2]), "r"(a[3]), "r"(b0), "r"(b1));
}
__device__ __forceinline__ void cp_async16(uint32_t dst, const void* src) {
    asm volatile("cp.async.cg.shared.global [%0], [%1], 16;" :: "r"(dst), "l"(src));
}
#define CP_COMMIT() asm volatile("cp.async.commit_group;" ::: "memory")
#define CP_WAIT(N)  asm volatile("cp.async.wait_group %0;" :: "n"(N) : "memory")

__device__ __forceinline__ uint32_t u32of(__half2 h) {
    return *reinterpret_cast<uint32_t*>(&h);
}
// fp32 pair -> (hi fp16x2, lo fp16x2)
__device__ __forceinline__ void cvt_hilo(float x, float y, uint32_t& hi, uint32_t& lo) {
    __half2 h = __floats2half2_rn(x, y);
    float2 hf = __half22float2(h);
    __half2 l = __floats2half2_rn(x - hf.x, y - hf.y);
    hi = u32of(h);
    lo = u32of(l);
}

// ---------------------------------------------------------------------------
// fp32 -> fp16 conversion kernels
// ---------------------------------------------------------------------------
__global__ void cvt_hl_kernel(const float* __restrict__ src,
                              __half* __restrict__ dh,
                              __half* __restrict__ dl, int n) {
    int i = (blockIdx.x * blockDim.x + threadIdx.x) * 4;
    if (i >= n) return;
    float4 f = *reinterpret_cast<const float4*>(src + i);
    uint32_t h0, l0, h1, l1;
    cvt_hilo(f.x, f.y, h0, l0);
    cvt_hilo(f.z, f.w, h1, l1);
    *reinterpret_cast<uint32_t*>(dh + i)     = h0;
    *reinterpret_cast<uint32_t*>(dh + i + 2) = h1;
    *reinterpret_cast<uint32_t*>(dl + i)     = l0;
    *reinterpret_cast<uint32_t*>(dl + i + 2) = l1;
}
__global__ void cvt_h_kernel(const float* __restrict__ src,
                             __half* __restrict__ dh, int n) {
    int i = (blockIdx.x * blockDim.x + threadIdx.x) * 4;
    if (i >= n) return;
    float4 f = *reinterpret_cast<const float4*>(src + i);
    *reinterpret_cast<uint32_t*>(dh + i)     = u32of(__floats2half2_rn(f.x, f.y));
    *reinterpret_cast<uint32_t*>(dh + i + 2) = u32of(__floats2half2_rn(f.z, f.w));
}

// ---------------------------------------------------------------------------
// RoPE: fp32 in -> rotated hi/lo fp16 out
// ---------------------------------------------------------------------------
__global__ void rope_cvt_kernel(const float* __restrict__ src,
                                const float* __restrict__ cosb,
                                const float* __restrict__ sinb,
                                __half* __restrict__ dh,
                                __half* __restrict__ dl, int H) {
    int idx = blockIdx.x * blockDim.x + threadIdx.x;
    int total = TSEQ * H * 32;
    if (idx >= total) return;
    int i = idx & 31;
    int h = (idx >> 5) % H;
    int t = idx / (32 * H);
    float c = cosb[t * 32 + i];
    float s = sinb[t * 32 + i];
    size_t off = ((size_t)t * H + h) * DHEAD + 2 * i;
    float x0 = src[off], x1 = src[off + 1];
    float o0 = x0 * c - x1 * s;
    float o1 = x0 * s + x1 * c;
    uint32_t hh, ll;
    cvt_hilo(o0, o1, hh, ll);
    *reinterpret_cast<uint32_t*>(dh + off) = hh;
    *reinterpret_cast<uint32_t*>(dl + off) = ll;
}

// ===========================================================================
// Projection GEMM: fp16 2-term ((Ahi+Alo)·Bhi), cp.async 2-stage pipeline.
// C[128,128] tile of A[M,2048] · B[N,2048]^T. 256 thr = 8 warps, 64x32/warp.
// ===========================================================================
#define GST 40                       // smem row stride in halves (80B)
#define TILE_H (128 * GST)           // halves per tile buffer (5120)
#define STAGE_H (3 * TILE_H)         // Ah, Al, Bh per stage
constexpr int GEMM_SMEM_BYTES = 2 * STAGE_H * 2;   // 61440

__device__ __forceinline__ void gemm_loads(uint32_t sb, int stage,
                                           const __half* Ah, const __half* Al,
                                           const __half* Bh, int k0, int tid) {
    const __half* bases[3] = {Ah, Al, Bh};
    uint32_t dbase = sb + (uint32_t)stage * STAGE_H * 2;
#pragma unroll
    for (int it = 0; it < 6; ++it) {
        int slot = tid + it * 256;      // 1536 slots: 3 tiles x 128 rows x 4
        int t = slot >> 9;
        int idx = slot & 511;
        int row = idx >> 2;
        int q = idx & 3;
        const void* src = bases[t] + (size_t)row * 2048 + k0 + q * 8;
        uint32_t dst = dbase + (uint32_t)(t * TILE_H + row * GST + q * 8) * 2;
        cp_async16(dst, src);
    }
}

__device__ void gemm_body(const __half* __restrict__ Ah,
                          const __half* __restrict__ Al,
                          const __half* __restrict__ Bh,
                          float* Cf, __half* Cv, int ldc, int vout) {
    extern __shared__ uint16_t sm16[];
    uint32_t sb = smem_u32(sm16);
    int tid = threadIdx.x;
    int lane = tid & 31;
    int wid = tid >> 5;
    int m0 = (wid & 1) * 64;
    int n0 = (wid >> 1) * 32;

    float acc[4][4][4];
#pragma unroll
    for (int i = 0; i < 4; ++i)
#pragma unroll
        for (int j = 0; j < 4; ++j)
#pragma unroll
            for (int q = 0; q < 4; ++q) acc[i][j][q] = 0.0f;

    gemm_loads(sb, 0, Ah, Al, Bh, 0, tid);
    CP_COMMIT();

    for (int i = 0; i < 64; ++i) {
        int s = i & 1;
        if (i < 63) {
            gemm_loads(sb, s ^ 1, Ah, Al, Bh, (i + 1) * 32, tid);
            CP_COMMIT();
            CP_WAIT(1);
        } else {
            CP_WAIT(0);
        }
        __syncthreads();

        uint32_t aAh = sb + (uint32_t)s * STAGE_H * 2;
        uint32_t aAl = aAh + TILE_H * 2;
        uint32_t aBh = aAl + TILE_H * 2;

#pragma unroll
        for (int kk = 0; kk < 2; ++kk) {
            uint32_t ah[4][4], al[4][4];
            int rA = m0 + (lane & 15);
            int cA = kk * 16 + ((lane >> 4) << 3);
#pragma unroll
            for (int i2 = 0; i2 < 4; ++i2) {
                uint32_t off = (uint32_t)(((rA + 16 * i2) * GST + cA) * 2);
                ldsm4(ah[i2], aAh + off);
                ldsm4(al[i2], aAl + off);
            }
            uint32_t bh[2][4];
            int rB = n0 + (lane & 7) + ((lane >> 3) & 1) * 8;
            int cB = kk * 16 + ((lane >> 4) << 3);
#pragma unroll
            for (int jp = 0; jp < 2; ++jp) {
                uint32_t off = (uint32_t)(((rB + 16 * jp) * GST + cB) * 2);
                ldsm4(bh[jp], aBh + off);
            }
            // term hi·hi
#pragma unroll
            for (int i2 = 0; i2 < 4; ++i2)
#pragma unroll
                for (int jp = 0; jp < 2; ++jp) {
                    mma_f16(acc[i2][2 * jp],     ah[i2], bh[jp][0], bh[jp][2]);
                    mma_f16(acc[i2][2 * jp + 1], ah[i2], bh[jp][1], bh[jp][3]);
                }
            // term lo·hi
#pragma unroll
            for (int i2 = 0; i2 < 4; ++i2)
#pragma unroll
                for (int jp = 0; jp < 2; ++jp) {
                    mma_f16(acc[i2][2 * jp],     al[i2], bh[jp][0], bh[jp][2]);
                    mma_f16(acc[i2][2 * jp + 1], al[i2], bh[jp][1], bh[jp][3]);
                }
        }
        __syncthreads();
    }

    int r = m0 + (lane >> 2);
    int cq = 2 * (lane & 3);
    if (!vout) {
#pragma unroll
        for (int i = 0; i < 4; ++i)
#pragma unroll
            for (int j = 0; j < 4; ++j) {
                int row = r + 16 * i;
                int col = n0 + 8 * j + cq;
                *reinterpret_cast<float2*>(Cf + (size_t)row * ldc + col) =
                    make_float2(acc[i][j][0], acc[i][j][1]);
                *reinterpret_cast<float2*>(Cf + (size_t)(row + 8) * ldc + col) =
                    make_float2(acc[i][j][2], acc[i][j][3]);
            }
    } else {
#pragma unroll
        for (int i = 0; i < 4; ++i)
#pragma unroll
            for (int j = 0; j < 4; ++j) {
                int row = r + 16 * i;
                int col = n0 + 8 * j + cq;
                *reinterpret_cast<uint32_t*>(Cv + (size_t)row * ldc + col) =
                    u32of(__floats2half2_rn(acc[i][j][0], acc[i][j][1]));
                *reinterpret_cast<uint32_t*>(Cv + (size_t)(row + 8) * ldc + col) =
                    u32of(__floats2half2_rn(acc[i][j][2], acc[i][j][3]));
            }
    }
}

// QKV projection: N = 2048 (Q) + 512 (K) + 512 (V -> single fp16)
__global__ __launch_bounds__(256) void qkv_hmma() {
    int bm = blockIdx.y * 128;
    int bn = blockIdx.x * 128;
    const __half* Ah = g_xh + (size_t)bm * DMODEL;
    const __half* Al = g_xl + (size_t)bm * DMODEL;
    const __half* Bh = g_wh + (size_t)bn * DMODEL;
    if (bn < 2048) {
        gemm_body(Ah, Al, Bh, g_q + (size_t)bm * DMODEL + bn, nullptr, DMODEL, 0);
    } else if (bn < 2560) {
        gemm_body(Ah, Al, Bh, g_k + (size_t)bm * DKV + (bn - 2048), nullptr, DKV, 0);
    } else {
        gemm_body(Ah, Al, Bh, nullptr,
                  g_vh + (size_t)bm * DKV + (bn - 2560), DKV, 1);
    }
}

__global__ __launch_bounds__(256) void out_hmma(float* __restrict__ out) {
    int bm = blockIdx.y * 128;
    int bn = blockIdx.x * 128;
    gemm_body(g_ah + (size_t)bm * DMODEL, g_al + (size_t)bm * DMODEL,
              g_woh + (size_t)bn * DMODEL,
              out + (size_t)bm * DMODEL + bn, nullptr, DMODEL, 0);
}

// ===========================================================================
// FA2-style causal GQA attention, fp16. QK 3-term; PV 2-term (V single hi).
// Triangle-balanced: grid (16, HQ); block does qt=bi then qt=31-bi.
// 128 threads (4 warps), 16 q-rows/warp, BS=64.
// ===========================================================================
#define AST 72   // smem row stride in halves (144B)
constexpr int ATTN_SMEM_BYTES = 5 * 64 * AST * 2;   // 46080

__global__ __launch_bounds__(128, 3) void attn_hmma() {
    extern __shared__ uint16_t sm16[];
    uint16_t* sQh = sm16;
    uint16_t* sQl = sQh + 64 * AST;
    uint16_t* sKh = sQl + 64 * AST;
    uint16_t* sKl = sKh + 64 * AST;
    uint16_t* sVh = sKl + 64 * AST;
    uint32_t aQh = smem_u32(sQh), aQl = smem_u32(sQl);
    uint32_t aKh = smem_u32(sKh), aKl = smem_u32(sKl);
    uint32_t aVh = smem_u32(sVh);

    int tid = threadIdx.x;
    int lane = tid & 31;
    int w = tid >> 5;
    int h = blockIdx.y;
    int kvh = h >> 2;
    const float SCALE = 0.125f;

    for (int pass = 0; pass < 2; ++pass) {
        int qt = pass == 0 ? (int)blockIdx.x : 31 - (int)blockIdx.x;

        __syncthreads();   // prior pass done before overwriting sQ
        // Load Q tile (fp16 hi/lo, 64 x 64)
        {
            const __half* qsrc[2] = {g_qh, g_ql};
            uint16_t* qdst[2] = {sQh, sQl};
#pragma unroll
            for (int it = 0; it < 8; ++it) {
                int slot = tid + it * 128;       // 1024 slots
                int t = slot >> 9;
                int r = (slot >> 3) & 63;
                int q = slot & 7;
                const __half* src =
                    qsrc[t] + (size_t)(qt * 64 + r) * DMODEL + h * DHEAD + q * 8;
                *reinterpret_cast<uint4*>(qdst[t] + r * AST + q * 8) =
                    *reinterpret_cast<const uint4*>(src);
            }
        }

        float m0 = -1e30f, m1 = -1e30f, l0 = 0.0f, l1 = 0.0f;
        float oac[8][4];
#pragma unroll
        for (int j = 0; j < 8; ++j)
#pragma unroll
            for (int q = 0; q < 4; ++q) oac[j][q] = 0.0f;

        for (int st = 0; st <= qt; ++st) {
            __syncthreads();
            // Load K hi/lo + V hi (64 x 64 each)
            {
                const __half* srcs[3] = {g_kh, g_kl, g_vh};
                uint16_t* dsts[3] = {sKh, sKl, sVh};
#pragma unroll
                for (int it = 0; it < 12; ++it) {
                    int slot = tid + it * 128;   // 1536 slots
                    int t = slot >> 9;
                    int r = (slot >> 3) & 63;
                    int q = slot & 7;
                    const __half* src =
                        srcs[t] + (size_t)(st * 64 + r) * DKV + kvh * DHEAD + q * 8;
                    *reinterpret_cast<uint4*>(dsts[t] + r * AST + q * 8) =
                        *reinterpret_cast<const uint4*>(src);
                }
            }
            __syncthreads();

            // ---- S = Q K^T (3-term: QhKh + QlKh + QhKl) ----
            float sa[8][4];
#pragma unroll
            for (int j = 0; j < 8; ++j)
#pragma unroll
                for (int q = 0; q < 4; ++q) sa[j][q] = 0.0f;

            int rQ = 16 * w + (lane & 15);
            int rB = (lane & 7) + ((lane >> 3) & 1) * 8;
            int cF = ((lane >> 4) << 3);
#pragma unroll
            for (int kk = 0; kk < 4; ++kk) {
                uint32_t qh[4], ql[4];
                uint32_t qoff = (uint32_t)((rQ * AST + cF + 16 * kk) * 2);
                ldsm4(qh, aQh + qoff);
                ldsm4(ql, aQl + qoff);
                uint32_t kb[4][4], kbl[4][4];
#pragma unroll
                for (int jp = 0; jp < 4; ++jp) {
                    uint32_t off = (uint32_t)(((rB + 16 * jp) * AST + cF + 16 * kk) * 2);
                    ldsm4(kb[jp], aKh + off);
                    ldsm4(kbl[jp], aKl + off);
                }
#pragma unroll
                for (int jp = 0; jp < 4; ++jp) {
                    mma_f16(sa[2 * jp],     qh, kb[jp][0], kb[jp][2]);
                    mma_f16(sa[2 * jp + 1], qh, kb[jp][1], kb[jp][3]);
                }
#pragma unroll
                for (int jp = 0; jp < 4; ++jp) {
                    mma_f16(sa[2 * jp],     ql, kb[jp][0], kb[jp][2]);
                    mma_f16(sa[2 * jp + 1], ql, kb[jp][1], kb[jp][3]);
                }
#pragma unroll
                for (int jp = 0; jp < 4; ++jp) {
                    mma_f16(sa[2 * jp],     qh, kbl[jp][0], kbl[jp][2]);
                    mma_f16(sa[2 * jp + 1], qh, kbl[jp][1], kbl[jp][3]);
                }
            }

            // ---- causal mask on diagonal tile ----
            if (st == qt) {
                int rloc = 16 * w + (lane >> 2);
#pragma unroll
                for (int j = 0; j < 8; ++j) {
                    int c = 8 * j + 2 * (lane & 3);
                    if (c > rloc)         sa[j][0] = -1e30f;
                    if (c + 1 > rloc)     sa[j][1] = -1e30f;
                    if (c > rloc + 8)     sa[j][2] = -1e30f;
                    if (c + 1 > rloc + 8) sa[j][3] = -1e30f;
                }
            }

            // ---- online softmax ----
            float rmax0 = -1e30f, rmax1 = -1e30f;
#pragma unroll
            for (int j = 0; j < 8; ++j) {
                rmax0 = fmaxf(rmax0, fmaxf(sa[j][0], sa[j][1]));
                rmax1 = fmaxf(rmax1, fmaxf(sa[j][2], sa[j][3]));
            }
#pragma unroll
            for (int off = 1; off < 4; off <<= 1) {
                rmax0 = fmaxf(rmax0, __shfl_xor_sync(0xffffffffu, rmax0, off));
                rmax1 = fmaxf(rmax1, __shfl_xor_sync(0xffffffffu, rmax1, off));
            }
            float mn0 = fmaxf(m0, SCALE * rmax0);
            float mn1 = fmaxf(m1, SCALE * rmax1);
            float al0 = __expf(m0 - mn0);
            float al1 = __expf(m1 - mn1);

            uint32_t pa[4][4], pl[4][4];
            float rs0 = 0.0f, rs1 = 0.0f;
#pragma unroll
            for (int j = 0; j < 8; ++j) {
                float p0 = __expf(fmaf(SCALE, sa[j][0], -mn0));
                float p1 = __expf(fmaf(SCALE, sa[j][1], -mn0));
                float p2 = __expf(fmaf(SCALE, sa[j][2], -mn1));
                float p3 = __expf(fmaf(SCALE, sa[j][3], -mn1));
                rs0 += p0 + p1;
                rs1 += p2 + p3;
                uint32_t h01, l01, h23, l23;
                cvt_hilo(p0, p1, h01, l01);
                cvt_hilo(p2, p3, h23, l23);
                pa[j >> 1][(j & 1) ? 2 : 0] = h01;
                pa[j >> 1][(j & 1) ? 3 : 1] = h23;
                pl[j >> 1][(j & 1) ? 2 : 0] = l01;
                pl[j >> 1][(j & 1) ? 3 : 1] = l23;
            }
#pragma unroll
            for (int off = 1; off < 4; off <<= 1) {
                rs0 += __shfl_xor_sync(0xffffffffu, rs0, off);
                rs1 += __shfl_xor_sync(0xffffffffu, rs1, off);
            }
            l0 = l0 * al0 + rs0;
            l1 = l1 * al1 + rs1;
            m0 = mn0;
            m1 = mn1;
#pragma unroll
            for (int j = 0; j < 8; ++j) {
                oac[j][0] *= al0;
                oac[j][1] *= al0;
                oac[j][2] *= al1;
                oac[j][3] *= al1;
            }

            // ---- O += (Phi + Plo) Vhi (2-term) ----
#pragma unroll
            for (int ks = 0; ks < 4; ++ks) {
                uint32_t vh[4][4];
                int row = 16 * ks + (lane & 7) + ((lane >> 3) & 1) * 8;
#pragma unroll
                for (int jp = 0; jp < 4; ++jp) {
                    int col = 16 * jp + ((lane >> 4) << 3);
                    uint32_t off = (uint32_t)((row * AST + col) * 2);
                    ldsm4t(vh[jp], aVh + off);
                }
#pragma unroll
                for (int jp = 0; jp < 4; ++jp) {
                    mma_f16(oac[2 * jp],     pa[ks], vh[jp][0], vh[jp][1]);
                    mma_f16(oac[2 * jp + 1], pa[ks], vh[jp][2], vh[jp][3]);
                }
#pragma unroll
                for (int jp = 0; jp < 4; ++jp) {
                    mma_f16(oac[2 * jp],     pl[ks], vh[jp][0], vh[jp][1]);
                    mma_f16(oac[2 * jp + 1], pl[ks], vh[jp][2], vh[jp][3]);
                }
            }
        }

        // Epilogue: normalize, fp16 hi/lo split for out-projection
        float inv0 = 1.0f / l0;
        float inv1 = 1.0f / l1;
        int row = qt * 64 + 16 * w + (lane >> 2);
        size_t ob = (size_t)row * DMODEL + h * DHEAD;
#pragma unroll
        for (int j = 0; j < 8; ++j) {
            int col = 8 * j + 2 * (lane & 3);
            uint32_t hh, ll;
            cvt_hilo(oac[j][0] * inv0, oac[j][1] * inv0, hh, ll);
            *reinterpret_cast<uint32_t*>(g_ah + ob + col) = hh;
            *reinterpret_cast<uint32_t*>(g_al + ob + col) = ll;
            cvt_hilo(oac[j][2] * inv1, oac[j][3] * inv1, hh, ll);
            *reinterpret_cast<uint32_t*>(g_ah + ob + (size_t)8 * DMODEL + col) = hh;
            *reinterpret_cast<uint32_t*>(g_al + ob + (size_t)8 * DMODEL + col) = ll;
        }
    }
}

// ---------------------------------------------------------------------------
extern "C" void kernel_launch(void* const* d_in, const int* in_sizes, int n_in,
                              void* d_out, int out_size) {
    const float* x  = (const float*)d_in[0];
    const float* Wq = (const float*)d_in[1];
    const float* Wk = (const float*)d_in[2];
    const float* Wv = (const float*)d_in[3];
    const float* Wo = (const float*)d_in[4];
    const float* rc = (const float*)d_in[5];
    const float* rs = (const float*)d_in[6];
    float* out = (float*)d_out;

    static bool attrs_set = false;
    if (!attrs_set) {
        cudaFuncSetAttribute(attn_hmma, cudaFuncAttributeMaxDynamicSharedMemorySize,
                             ATTN_SMEM_BYTES);
        cudaFuncSetAttribute(qkv_hmma, cudaFuncAttributeMaxDynamicSharedMemorySize,
                             GEMM_SMEM_BYTES);
        cudaFuncSetAttribute(out_hmma, cudaFuncAttributeMaxDynamicSharedMemorySize,
                             GEMM_SMEM_BYTES);
        attrs_set = true;
    }

    __half *d_xh, *d_xl, *d_wh, *d_woh, *d_qh, *d_ql, *d_kh, *d_kl;
    float *d_q, *d_k;
    cudaGetSymbolAddress((void**)&d_xh, g_xh);
    cudaGetSymbolAddress((void**)&d_xl, g_xl);
    cudaGetSymbolAddress((void**)&d_wh, g_wh);
    cudaGetSymbolAddress((void**)&d_woh, g_woh);
    cudaGetSymbolAddress((void**)&d_qh, g_qh);
    cudaGetSymbolAddress((void**)&d_ql, g_ql);
    cudaGetSymbolAddress((void**)&d_kh, g_kh);
    cudaGetSymbolAddress((void**)&d_kl, g_kl);
    cudaGetSymbolAddress((void**)&d_q, g_q);
    cudaGetSymbolAddress((void**)&d_k, g_k);

    // 0) Pre-convert inputs (x: hi+lo; weights: hi only)
    {
        int n;
        n = TSEQ * DMODEL;
        cvt_hl_kernel<<<n / 1024, 256>>>(x, d_xh, d_xl, n);
        n = 2048 * DMODEL;
        cvt_h_kernel<<<n / 1024, 256>>>(Wq, d_wh, n);
        n = 512 * DMODEL;
        cvt_h_kernel<<<n / 1024, 256>>>(Wk, d_wh + (size_t)2048 * DMODEL, n);
        cvt_h_kernel<<<n / 1024, 256>>>(Wv, d_wh + (size_t)2560 * DMODEL, n);
        n = DMODEL * DMODEL;
        cvt_h_kernel<<<n / 1024, 256>>>(Wo, d_woh, n);
    }

    // 1) Fused QKV projection (fp16 2-term HMMA)
    qkv_hmma<<<dim3(24, 16), 256, GEMM_SMEM_BYTES>>>();

    // 2) RoPE + fp16 hi/lo conversion for Q and K
    {
        int totq = TSEQ * HQ * 32;
        rope_cvt_kernel<<<(totq + 255) / 256, 256>>>(d_q, rc, rs, d_qh, d_ql, HQ);
        int totk = TSEQ * HKV * 32;
        rope_cvt_kernel<<<(totk + 255) / 256, 256>>>(d_k, rc, rs, d_kh, d_kl, HKV);
    }

    // 3) Causal GQA attention (fp16; QK 3-term, PV 2-term)
    attn_hmma<<<dim3(16, HQ), 128, ATTN_SMEM_BYTES>>>();

    // 4) Output projection (fp16 2-term)
    out_hmma<<<dim3(16, 16), 256, GEMM_SMEM_BYTES>>>(out);
}

// round 8
// speedup vs baseline: 2.1204x; 1.6044x over previous
#include <cuda_runtime.h>
#include <cuda_fp16.h>
#include <math.h>
#include <cstdint>

// Problem constants
#define TSEQ 2048
#define DMODEL 2048
#define HQ 32
#define HKV 8
#define DHEAD 64
#define DKV (HKV * DHEAD)   // 512

// ---------------------------------------------------------------------------
// Device-global scratch (allocation-free rule). fp16 arrays 16B-aligned.
// ---------------------------------------------------------------------------
__device__ float g_q[TSEQ * DMODEL];                       // fp32 Q pre-rope
__device__ float g_k[TSEQ * DKV];                          // fp32 K pre-rope
__device__ __align__(16) __half g_xh[TSEQ * DMODEL];
__device__ __align__(16) __half g_wh[3072 * DMODEL];
__device__ __align__(16) __half g_woh[DMODEL * DMODEL];
__device__ __align__(16) __half g_qh[TSEQ * DMODEL];
__device__ __align__(16) __half g_kh[TSEQ * DKV];
__device__ __align__(16) __half g_vh[TSEQ * DKV];
__device__ __align__(16) __half g_ah[TSEQ * DMODEL];

// ===========================================================================
// Warp-MMA / async-copy helpers (sm_80+ baseline; no sm_103a-only features)
// ===========================================================================
__device__ __forceinline__ uint32_t smem_u32(const void* p) {
    uint32_t a;
    asm("{ .reg .u64 t; cvta.to.shared.u64 t, %1; cvt.u32.u64 %0, t; }"
        : "=r"(a) : "l"(p));
    return a;
}
__device__ __forceinline__ void ldsm4(uint32_t* r, uint32_t a) {
    asm volatile("ldmatrix.sync.aligned.m8n8.x4.shared.b16 {%0,%1,%2,%3}, [%4];"
                 : "=r"(r[0]), "=r"(r[1]), "=r"(r[2]), "=r"(r[3]) : "r"(a));
}
__device__ __forceinline__ void ldsm4t(uint32_t* r, uint32_t a) {
    asm volatile("ldmatrix.sync.aligned.m8n8.x4.trans.shared.b16 {%0,%1,%2,%3}, [%4];"
                 : "=r"(r[0]), "=r"(r[1]), "=r"(r[2]), "=r"(r[3]) : "r"(a));
}
// D += A * B  (m16n8k16, fp16 in, fp32 acc)
__device__ __forceinline__ void mma_f16(float* c, const uint32_t* a,
                                        uint32_t b0, uint32_t b1) {
    asm volatile(
        "mma.sync.aligned.m16n8k16.row.col.f32.f16.f16.f32 "
        "{%0,%1,%2,%3}, {%4,%5,%6,%7}, {%8,%9}, {%0,%1,%2,%3};"
        : "+f"(c[0]), "+f"(c[1]), "+f"(c[2]), "+f"(c[3])
        : "r"(a[0]), "r"(a[1]), "r"(a[2]), "r"(a[3]), "r"(b0), "r"(b1));
}
__device__ __forceinline__ void cp_async16(uint32_t dst, const void* src) {
    asm volatile("cp.async.cg.shared.global [%0], [%1], 16;" :: "r"(dst), "l"(src));
}
#define CP_COMMIT() asm volatile("cp.async.commit_group;" ::: "memory")
#define CP_WAIT(N)  asm volatile("cp.async.wait_group %0;" :: "n"(N) : "memory")

__device__ __forceinline__ uint32_t u32of(__half2 h) {
    return *reinterpret_cast<uint32_t*>(&h);
}

// ---------------------------------------------------------------------------
// fp32 -> fp16 conversion kernel
// ---------------------------------------------------------------------------
__global__ void cvt_h_kernel(const float* __restrict__ src,
                             __half* __restrict__ dh, int n) {
    int i = (blockIdx.x * blockDim.x + threadIdx.x) * 4;
    if (i >= n) return;
    float4 f = *reinterpret_cast<const float4*>(src + i);
    *reinterpret_cast<uint32_t*>(dh + i)     = u32of(__floats2half2_rn(f.x, f.y));
    *reinterpret_cast<uint32_t*>(dh + i + 2) = u32of(__floats2half2_rn(f.z, f.w));
}

// ---------------------------------------------------------------------------
// RoPE: fp32 in -> rotated fp16 out
// ---------------------------------------------------------------------------
__global__ void rope_cvt_kernel(const float* __restrict__ src,
                                const float* __restrict__ cosb,
                                const float* __restrict__ sinb,
                                __half* __restrict__ dh, int H) {
    int idx = blockIdx.x * blockDim.x + threadIdx.x;
    int total = TSEQ * H * 32;
    if (idx >= total) return;
    int i = idx & 31;
    int h = (idx >> 5) % H;
    int t = idx / (32 * H);
    float c = cosb[t * 32 + i];
    float s = sinb[t * 32 + i];
    size_t off = ((size_t)t * H + h) * DHEAD + 2 * i;
    float x0 = src[off], x1 = src[off + 1];
    float o0 = x0 * c - x1 * s;
    float o1 = x0 * s + x1 * c;
    *reinterpret_cast<uint32_t*>(dh + off) = u32of(__floats2half2_rn(o0, o1));
}

// ===========================================================================
// Projection GEMM: single fp16, cp.async 2-stage pipeline.
// C[128,128] tile of A[M,2048] · B[N,2048]^T. 256 thr = 8 warps, 64x32/warp.
// ===========================================================================
#define GST 40                       // smem row stride in halves (80B)
#define TILE_H (128 * GST)           // halves per tile buffer (5120)
#define STAGE_H (2 * TILE_H)         // A, B per stage
constexpr int GEMM_SMEM_BYTES = 2 * STAGE_H * 2;   // 40960

__device__ __forceinline__ void gemm_loads(uint32_t sb, int stage,
                                           const __half* A, const __half* B,
                                           int k0, int tid) {
    const __half* bases[2] = {A, B};
    uint32_t dbase = sb + (uint32_t)stage * STAGE_H * 2;
#pragma unroll
    for (int it = 0; it < 4; ++it) {
        int slot = tid + it * 256;      // 1024 slots: 2 tiles x 128 rows x 4
        int t = slot >> 9;
        int idx = slot & 511;
        int row = idx >> 2;
        int q = idx & 3;
        const void* src = bases[t] + (size_t)row * 2048 + k0 + q * 8;
        uint32_t dst = dbase + (uint32_t)(t * TILE_H + row * GST + q * 8) * 2;
        cp_async16(dst, src);
    }
}

__device__ void gemm_body(const __half* __restrict__ A,
                          const __half* __restrict__ B,
                          float* Cf, __half* Cv, int ldc, int vout) {
    extern __shared__ uint16_t sm16[];
    uint32_t sb = smem_u32(sm16);
    int tid = threadIdx.x;
    int lane = tid & 31;
    int wid = tid >> 5;
    int m0 = (wid & 1) * 64;
    int n0 = (wid >> 1) * 32;

    float acc[4][4][4];
#pragma unroll
    for (int i = 0; i < 4; ++i)
#pragma unroll
        for (int j = 0; j < 4; ++j)
#pragma unroll
            for (int q = 0; q < 4; ++q) acc[i][j][q] = 0.0f;

    gemm_loads(sb, 0, A, B, 0, tid);
    CP_COMMIT();

    for (int i = 0; i < 64; ++i) {
        int s = i & 1;
        if (i < 63) {
            gemm_loads(sb, s ^ 1, A, B, (i + 1) * 32, tid);
            CP_COMMIT();
            CP_WAIT(1);
        } else {
            CP_WAIT(0);
        }
        __syncthreads();

        uint32_t aA = sb + (uint32_t)s * STAGE_H * 2;
        uint32_t aB = aA + TILE_H * 2;

#pragma unroll
        for (int kk = 0; kk < 2; ++kk) {
            uint32_t ah[4][4];
            int rA = m0 + (lane & 15);
            int cA = kk * 16 + ((lane >> 4) << 3);
#pragma unroll
            for (int i2 = 0; i2 < 4; ++i2)
                ldsm4(ah[i2], aA + (uint32_t)(((rA + 16 * i2) * GST + cA) * 2));
            uint32_t bh[2][4];
            int rB = n0 + (lane & 7) + ((lane >> 3) & 1) * 8;
            int cB = kk * 16 + ((lane >> 4) << 3);
#pragma unroll
            for (int jp = 0; jp < 2; ++jp)
                ldsm4(bh[jp], aB + (uint32_t)(((rB + 16 * jp) * GST + cB) * 2));
#pragma unroll
            for (int i2 = 0; i2 < 4; ++i2)
#pragma unroll
                for (int jp = 0; jp < 2; ++jp) {
                    mma_f16(acc[i2][2 * jp],     ah[i2], bh[jp][0], bh[jp][2]);
                    mma_f16(acc[i2][2 * jp + 1], ah[i2], bh[jp][1], bh[jp][3]);
                }
        }
        __syncthreads();
    }

    int r = m0 + (lane >> 2);
    int cq = 2 * (lane & 3);
    if (!vout) {
#pragma unroll
        for (int i = 0; i < 4; ++i)
#pragma unroll
            for (int j = 0; j < 4; ++j) {
                int row = r + 16 * i;
                int col = n0 + 8 * j + cq;
                *reinterpret_cast<float2*>(Cf + (size_t)row * ldc + col) =
                    make_float2(acc[i][j][0], acc[i][j][1]);
                *reinterpret_cast<float2*>(Cf + (size_t)(row + 8) * ldc + col) =
                    make_float2(acc[i][j][2], acc[i][j][3]);
            }
    } else {
#pragma unroll
        for (int i = 0; i < 4; ++i)
#pragma unroll
            for (int j = 0; j < 4; ++j) {
                int row = r + 16 * i;
                int col = n0 + 8 * j + cq;
                *reinterpret_cast<uint32_t*>(Cv + (size_t)row * ldc + col) =
                    u32of(__floats2half2_rn(acc[i][j][0], acc[i][j][1]));
                *reinterpret_cast<uint32_t*>(Cv + (size_t)(row + 8) * ldc + col) =
                    u32of(__floats2half2_rn(acc[i][j][2], acc[i][j][3]));
            }
    }
}

// QKV projection: N = 2048 (Q) + 512 (K) + 512 (V -> single fp16)
__global__ __launch_bounds__(256) void qkv_hmma() {
    int bm = blockIdx.y * 128;
    int bn = blockIdx.x * 128;
    const __half* A = g_xh + (size_t)bm * DMODEL;
    const __half* B = g_wh + (size_t)bn * DMODEL;
    if (bn < 2048) {
        gemm_body(A, B, g_q + (size_t)bm * DMODEL + bn, nullptr, DMODEL, 0);
    } else if (bn < 2560) {
        gemm_body(A, B, g_k + (size_t)bm * DKV + (bn - 2048), nullptr, DKV, 0);
    } else {
        gemm_body(A, B, nullptr, g_vh + (size_t)bm * DKV + (bn - 2560), DKV, 1);
    }
}

__global__ __launch_bounds__(256) void out_hmma(float* __restrict__ out) {
    int bm = blockIdx.y * 128;
    int bn = blockIdx.x * 128;
    gemm_body(g_ah + (size_t)bm * DMODEL, g_woh + (size_t)bn * DMODEL,
              out + (size_t)bm * DMODEL + bn, nullptr, DMODEL, 0);
}

// ===========================================================================
// FA2-style causal GQA attention, single fp16.
// Triangle-balanced: grid (16, HQ); block does qt=bi then qt=31-bi.
// 128 threads (4 warps), 16 q-rows/warp, BS=64.
// ===========================================================================
#define AST 72   // smem row stride in halves (144B)
constexpr int ATTN_SMEM_BYTES = 3 * 64 * AST * 2;   // 27648

__global__ __launch_bounds__(128, 3) void attn_hmma() {
    extern __shared__ uint16_t sm16[];
    uint16_t* sQ = sm16;
    uint16_t* sK = sQ + 64 * AST;
    uint16_t* sV = sK + 64 * AST;
    uint32_t aQ = smem_u32(sQ), aK = smem_u32(sK), aV = smem_u32(sV);

    int tid = threadIdx.x;
    int lane = tid & 31;
    int w = tid >> 5;
    int h = blockIdx.y;
    int kvh = h >> 2;
    const float SCALE = 0.125f;

    for (int pass = 0; pass < 2; ++pass) {
        int qt = pass == 0 ? (int)blockIdx.x : 31 - (int)blockIdx.x;

        __syncthreads();   // prior pass done before overwriting sQ
        // Load Q tile (fp16, 64 x 64)
        {
#pragma unroll
            for (int it = 0; it < 4; ++it) {
                int slot = tid + it * 128;       // 512 slots
                int r = slot >> 3;
                int q = slot & 7;
                const __half* src =
                    g_qh + (size_t)(qt * 64 + r) * DMODEL + h * DHEAD + q * 8;
                *reinterpret_cast<uint4*>(sQ + r * AST + q * 8) =
                    *reinterpret_cast<const uint4*>(src);
            }
        }

        float m0 = -1e30f, m1 = -1e30f, l0 = 0.0f, l1 = 0.0f;
        float oac[8][4];
#pragma unroll
        for (int j = 0; j < 8; ++j)
#pragma unroll
            for (int q = 0; q < 4; ++q) oac[j][q] = 0.0f;

        // Q fragments live in registers across the KV loop (single term)
        uint32_t qf[4][4];
        {
            __syncthreads();
            int rQ = 16 * w + (lane & 15);
            int cF = ((lane >> 4) << 3);
#pragma unroll
            for (int kk = 0; kk < 4; ++kk)
                ldsm4(qf[kk], aQ + (uint32_t)((rQ * AST + cF + 16 * kk) * 2));
        }

        for (int st = 0; st <= qt; ++st) {
            __syncthreads();
            // Load K + V (fp16, 64 x 64 each)
            {
                const __half* srcs[2] = {g_kh, g_vh};
                uint16_t* dsts[2] = {sK, sV};
#pragma unroll
                for (int it = 0; it < 8; ++it) {
                    int slot = tid + it * 128;   // 1024 slots
                    int t = slot >> 9;
                    int r = (slot >> 3) & 63;
                    int q = slot & 7;
                    const __half* src =
                        srcs[t] + (size_t)(st * 64 + r) * DKV + kvh * DHEAD + q * 8;
                    *reinterpret_cast<uint4*>(dsts[t] + r * AST + q * 8) =
                        *reinterpret_cast<const uint4*>(src);
                }
            }
            __syncthreads();

            // ---- S = Q K^T (single term) ----
            float sa[8][4];
#pragma unroll
            for (int j = 0; j < 8; ++j)
#pragma unroll
                for (int q = 0; q < 4; ++q) sa[j][q] = 0.0f;

            int rB = (lane & 7) + ((lane >> 3) & 1) * 8;
            int cF = ((lane >> 4) << 3);
#pragma unroll
            for (int kk = 0; kk < 4; ++kk) {
                uint32_t kb[4][4];
#pragma unroll
                for (int jp = 0; jp < 4; ++jp)
                    ldsm4(kb[jp], aK + (uint32_t)(((rB + 16 * jp) * AST + cF + 16 * kk) * 2));
#pragma unroll
                for (int jp = 0; jp < 4; ++jp) {
                    mma_f16(sa[2 * jp],     qf[kk], kb[jp][0], kb[jp][2]);
                    mma_f16(sa[2 * jp + 1], qf[kk], kb[jp][1], kb[jp][3]);
                }
            }

            // ---- causal mask on diagonal tile ----
            if (st == qt) {
                int rloc = 16 * w + (lane >> 2);
#pragma unroll
                for (int j = 0; j < 8; ++j) {
                    int c = 8 * j + 2 * (lane & 3);
                    if (c > rloc)         sa[j][0] = -1e30f;
                    if (c + 1 > rloc)     sa[j][1] = -1e30f;
                    if (c > rloc + 8)     sa[j][2] = -1e30f;
                    if (c + 1 > rloc + 8) sa[j][3] = -1e30f;
                }
            }

            // ---- online softmax ----
            float rmax0 = -1e30f, rmax1 = -1e30f;
#pragma unroll
            for (int j = 0; j < 8; ++j) {
                rmax0 = fmaxf(rmax0, fmaxf(sa[j][0], sa[j][1]));
                rmax1 = fmaxf(rmax1, fmaxf(sa[j][2], sa[j][3]));
            }
#pragma unroll
            for (int off = 1; off < 4; off <<= 1) {
                rmax0 = fmaxf(rmax0, __shfl_xor_sync(0xffffffffu, rmax0, off));
                rmax1 = fmaxf(rmax1, __shfl_xor_sync(0xffffffffu, rmax1, off));
            }
            float mn0 = fmaxf(m0, SCALE * rmax0);
            float mn1 = fmaxf(m1, SCALE * rmax1);
            float al0 = __expf(m0 - mn0);
            float al1 = __expf(m1 - mn1);

            uint32_t pa[4][4];
            float rs0 = 0.0f, rs1 = 0.0f;
#pragma unroll
            for (int j = 0; j < 8; ++j) {
                float p0 = __expf(fmaf(SCALE, sa[j][0], -mn0));
                float p1 = __expf(fmaf(SCALE, sa[j][1], -mn0));
                float p2 = __expf(fmaf(SCALE, sa[j][2], -mn1));
                float p3 = __expf(fmaf(SCALE, sa[j][3], -mn1));
                rs0 += p0 + p1;
                rs1 += p2 + p3;
                pa[j >> 1][(j & 1) ? 2 : 0] = u32of(__floats2half2_rn(p0, p1));
                pa[j >> 1][(j & 1) ? 3 : 1] = u32of(__floats2half2_rn(p2, p3));
            }
#pragma unroll
            for (int off = 1; off < 4; off <<= 1) {
                rs0 += __shfl_xor_sync(0xffffffffu, rs0, off);
                rs1 += __shfl_xor_sync(0xffffffffu, rs1, off);
            }
            l0 = l0 * al0 + rs0;
            l1 = l1 * al1 + rs1;
            m0 = mn0;
            m1 = mn1;
#pragma unroll
            for (int j = 0; j < 8; ++j) {
                oac[j][0] *= al0;
                oac[j][1] *= al0;
                oac[j][2] *= al1;
                oac[j][3] *= al1;
            }

            // ---- O += P V (single term) ----
#pragma unroll
            for (int ks = 0; ks < 4; ++ks) {
                uint32_t vh[4][4];
                int row = 16 * ks + (lane & 7) + ((lane >> 3) & 1) * 8;
#pragma unroll
                for (int jp = 0; jp < 4; ++jp) {
                    int col = 16 * jp + ((lane >> 4) << 3);
                    ldsm4t(vh[jp], aV + (uint32_t)((row * AST + col) * 2));
                }
#pragma unroll
                for (int jp = 0; jp < 4; ++jp) {
                    mma_f16(oac[2 * jp],     pa[ks], vh[jp][0], vh[jp][1]);
                    mma_f16(oac[2 * jp + 1], pa[ks], vh[jp][2], vh[jp][3]);
                }
            }
        }

        // Epilogue: normalize, single fp16 out for out-projection
        float inv0 = 1.0f / l0;
        float inv1 = 1.0f / l1;
        int row = qt * 64 + 16 * w + (lane >> 2);
        size_t ob = (size_t)row * DMODEL + h * DHEAD;
#pragma unroll
        for (int j = 0; j < 8; ++j) {
            int col = 8 * j + 2 * (lane & 3);
            *reinterpret_cast<uint32_t*>(g_ah + ob + col) =
                u32of(__floats2half2_rn(oac[j][0] * inv0, oac[j][1] * inv0));
            *reinterpret_cast<uint32_t*>(g_ah + ob + (size_t)8 * DMODEL + col) =
                u32of(__floats2half2_rn(oac[j][2] * inv1, oac[j][3] * inv1));
        }
    }
}

// ---------------------------------------------------------------------------
extern "C" void kernel_launch(void* const* d_in, const int* in_sizes, int n_in,
                              void* d_out, int out_size) {
    const float* x  = (const float*)d_in[0];
    const float* Wq = (const float*)d_in[1];
    const float* Wk = (const float*)d_in[2];
    const float* Wv = (const float*)d_in[3];
    const float* Wo = (const float*)d_in[4];
    const float* rc = (const float*)d_in[5];
    const float* rs = (const float*)d_in[6];
    float* out = (float*)d_out;

    static bool attrs_set = false;
    if (!attrs_set) {
        cudaFuncSetAttribute(attn_hmma, cudaFuncAttributeMaxDynamicSharedMemorySize,
                             ATTN_SMEM_BYTES);
        cudaFuncSetAttribute(qkv_hmma, cudaFuncAttributeMaxDynamicSharedMemorySize,
                             GEMM_SMEM_BYTES);
        cudaFuncSetAttribute(out_hmma, cudaFuncAttributeMaxDynamicSharedMemorySize,
                             GEMM_SMEM_BYTES);
        attrs_set = true;
    }

    __half *d_xh, *d_wh, *d_woh, *d_qh, *d_kh;
    float *d_q, *d_k;
    cudaGetSymbolAddress((void**)&d_xh, g_xh);
    cudaGetSymbolAddress((void**)&d_wh, g_wh);
    cudaGetSymbolAddress((void**)&d_woh, g_woh);
    cudaGetSymbolAddress((void**)&d_qh, g_qh);
    cudaGetSymbolAddress((void**)&d_kh, g_kh);
    cudaGetSymbolAddress((void**)&d_q, g_q);
    cudaGetSymbolAddress((void**)&d_k, g_k);

    // 0) Pre-convert inputs to single fp16
    {
        int n;
        n = TSEQ * DMODEL;
        cvt_h_kernel<<<n / 1024, 256>>>(x, d_xh, n);
        n = 2048 * DMODEL;
        cvt_h_kernel<<<n / 1024, 256>>>(Wq, d_wh, n);
        n = 512 * DMODEL;
        cvt_h_kernel<<<n / 1024, 256>>>(Wk, d_wh + (size_t)2048 * DMODEL, n);
        cvt_h_kernel<<<n / 1024, 256>>>(Wv, d_wh + (size_t)2560 * DMODEL, n);
        n = DMODEL * DMODEL;
        cvt_h_kernel<<<n / 1024, 256>>>(Wo, d_woh, n);
    }

    // 1) Fused QKV projection (single fp16 HMMA)
    qkv_hmma<<<dim3(24, 16), 256, GEMM_SMEM_BYTES>>>();

    // 2) RoPE + fp16 conversion for Q and K
    {
        int totq = TSEQ * HQ * 32;
        rope_cvt_kernel<<<(totq + 255) / 256, 256>>>(d_q, rc, rs, d_qh, HQ);
        int totk = TSEQ * HKV * 32;
        rope_cvt_kernel<<<(totk + 255) / 256, 256>>>(d_k, rc, rs, d_kh, HKV);
    }

    // 3) Causal GQA attention (single fp16)
    attn_hmma<<<dim3(16, HQ), 128, ATTN_SMEM_BYTES>>>();

    // 4) Output projection (single fp16)
    out_hmma<<<dim3(16, 16), 256, GEMM_SMEM_BYTES>>>(out);
}

// round 9
// speedup vs baseline: 2.3411x; 1.1041x over previous
#include <cuda_runtime.h>
#include <cuda_fp16.h>
#include <math.h>
#include <cstdint>

// Problem constants
#define TSEQ 2048
#define DMODEL 2048
#define HQ 32
#define HKV 8
#define DHEAD 64
#define DKV (HKV * DHEAD)   // 512

// ---------------------------------------------------------------------------
// Device-global scratch (allocation-free rule). fp16 arrays 16B-aligned.
// ---------------------------------------------------------------------------
__device__ __align__(16) __half g_xh[TSEQ * DMODEL];
__device__ __align__(16) __half g_wh[3072 * DMODEL];
__device__ __align__(16) __half g_woh[DMODEL * DMODEL];
__device__ __align__(16) __half g_qh[TSEQ * DMODEL];
__device__ __align__(16) __half g_kh[TSEQ * DKV];
__device__ __align__(16) __half g_vh[TSEQ * DKV];
__device__ __align__(16) __half g_ah[TSEQ * DMODEL];

// ===========================================================================
// Warp-MMA / async-copy helpers (sm_80+ baseline; no sm_103a-only features)
// ===========================================================================
__device__ __forceinline__ uint32_t smem_u32(const void* p) {
    uint32_t a;
    asm("{ .reg .u64 t; cvta.to.shared.u64 t, %1; cvt.u32.u64 %0, t; }"
        : "=r"(a) : "l"(p));
    return a;
}
__device__ __forceinline__ void ldsm4(uint32_t* r, uint32_t a) {
    asm volatile("ldmatrix.sync.aligned.m8n8.x4.shared.b16 {%0,%1,%2,%3}, [%4];"
                 : "=r"(r[0]), "=r"(r[1]), "=r"(r[2]), "=r"(r[3]) : "r"(a));
}
__device__ __forceinline__ void ldsm4t(uint32_t* r, uint32_t a) {
    asm volatile("ldmatrix.sync.aligned.m8n8.x4.trans.shared.b16 {%0,%1,%2,%3}, [%4];"
                 : "=r"(r[0]), "=r"(r[1]), "=r"(r[2]), "=r"(r[3]) : "r"(a));
}
// D += A * B  (m16n8k16, fp16 in, fp32 acc)
__device__ __forceinline__ void mma_f16(float* c, const uint32_t* a,
                                        uint32_t b0, uint32_t b1) {
    asm volatile(
        "mma.sync.aligned.m16n8k16.row.col.f32.f16.f16.f32 "
        "{%0,%1,%2,%3}, {%4,%5,%6,%7}, {%8,%9}, {%0,%1,%2,%3};"
        : "+f"(c[0]), "+f"(c[1]), "+f"(c[2]), "+f"(c[3])
        : "r"(a[0]), "r"(a[1]), "r"(a[2]), "r"(a[3]), "r"(b0), "r"(b1));
}
__device__ __forceinline__ void cp_async16(uint32_t dst, const void* src) {
    asm volatile("cp.async.cg.shared.global [%0], [%1], 16;" :: "r"(dst), "l"(src));
}
#define CP_COMMIT() asm volatile("cp.async.commit_group;" ::: "memory")
#define CP_WAIT(N)  asm volatile("cp.async.wait_group %0;" :: "n"(N) : "memory")

__device__ __forceinline__ uint32_t u32of(__half2 h) {
    return *reinterpret_cast<uint32_t*>(&h);
}

// ---------------------------------------------------------------------------
// Fused fp32 -> fp16 conversion for all 5 inputs (one launch)
// Regions (in float4 units): x 1048576 | Wq 1048576 | Wk 262144 | Wv 262144 | Wo 1048576
// ---------------------------------------------------------------------------
#define N4X 1048576
#define N4K 262144
__global__ void cvt_all_kernel(const float* __restrict__ x,
                               const float* __restrict__ Wq,
                               const float* __restrict__ Wk,
                               const float* __restrict__ Wv,
                               const float* __restrict__ Wo) {
    int i4 = blockIdx.x * blockDim.x + threadIdx.x;   // float4 index
    const float* src;
    __half* dst;
    int off;
    if (i4 < N4X) {
        src = x; dst = g_xh; off = i4;
    } else if (i4 < 2 * N4X) {
        src = Wq; dst = g_wh; off = i4 - N4X;
    } else if (i4 < 2 * N4X + N4K) {
        src = Wk; dst = g_wh + (size_t)2048 * DMODEL; off = i4 - 2 * N4X;
    } else if (i4 < 2 * N4X + 2 * N4K) {
        src = Wv; dst = g_wh + (size_t)2560 * DMODEL; off = i4 - 2 * N4X - N4K;
    } else {
        src = Wo; dst = g_woh; off = i4 - 2 * N4X - 2 * N4K;
    }
    float4 f = *reinterpret_cast<const float4*>(src + (size_t)off * 4);
    size_t o = (size_t)off * 4;
    *reinterpret_cast<uint32_t*>(dst + o)     = u32of(__floats2half2_rn(f.x, f.y));
    *reinterpret_cast<uint32_t*>(dst + o + 2) = u32of(__floats2half2_rn(f.z, f.w));
}

// ===========================================================================
// Projection GEMM: single fp16, cp.async 2-stage pipeline.
// C[128,128] tile of A[M,2048] · B[N,2048]^T. 256 thr = 8 warps, 64x32/warp.
// mode 0: fp32 out; mode 1: fp16 out; mode 2: RoPE + fp16 out.
// ===========================================================================
#define GST 40                       // smem row stride in halves (80B)
#define TILE_H (128 * GST)           // halves per tile buffer (5120)
#define STAGE_H (2 * TILE_H)         // A, B per stage
constexpr int GEMM_SMEM_BYTES = 2 * STAGE_H * 2;   // 40960

__device__ __forceinline__ void gemm_loads(uint32_t sb, int stage,
                                           const __half* A, const __half* B,
                                           int k0, int tid) {
    const __half* bases[2] = {A, B};
    uint32_t dbase = sb + (uint32_t)stage * STAGE_H * 2;
#pragma unroll
    for (int it = 0; it < 4; ++it) {
        int slot = tid + it * 256;      // 1024 slots: 2 tiles x 128 rows x 4
        int t = slot >> 9;
        int idx = slot & 511;
        int row = idx >> 2;
        int q = idx & 3;
        const void* src = bases[t] + (size_t)row * 2048 + k0 + q * 8;
        uint32_t dst = dbase + (uint32_t)(t * TILE_H + row * GST + q * 8) * 2;
        cp_async16(dst, src);
    }
}

__device__ void gemm_body(const __half* __restrict__ A,
                          const __half* __restrict__ B,
                          int mode, float* Cf, __half* Ch, int ldc,
                          const float* __restrict__ rc,
                          const float* __restrict__ rs,
                          int rbase, int cb) {
    extern __shared__ uint16_t sm16[];
    uint32_t sb = smem_u32(sm16);
    int tid = threadIdx.x;
    int lane = tid & 31;
    int wid = tid >> 5;
    int m0 = (wid & 1) * 64;
    int n0 = (wid >> 1) * 32;

    float acc[4][4][4];
#pragma unroll
    for (int i = 0; i < 4; ++i)
#pragma unroll
        for (int j = 0; j < 4; ++j)
#pragma unroll
            for (int q = 0; q < 4; ++q) acc[i][j][q] = 0.0f;

    gemm_loads(sb, 0, A, B, 0, tid);
    CP_COMMIT();

    for (int i = 0; i < 64; ++i) {
        int s = i & 1;
        if (i < 63) {
            gemm_loads(sb, s ^ 1, A, B, (i + 1) * 32, tid);
            CP_COMMIT();
            CP_WAIT(1);
        } else {
            CP_WAIT(0);
        }
        __syncthreads();

        uint32_t aA = sb + (uint32_t)s * STAGE_H * 2;
        uint32_t aB = aA + TILE_H * 2;

#pragma unroll
        for (int kk = 0; kk < 2; ++kk) {
            uint32_t ah[4][4];
            int rA = m0 + (lane & 15);
            int cA = kk * 16 + ((lane >> 4) << 3);
#pragma unroll
            for (int i2 = 0; i2 < 4; ++i2)
                ldsm4(ah[i2], aA + (uint32_t)(((rA + 16 * i2) * GST + cA) * 2));
            uint32_t bh[2][4];
            int rB = n0 + (lane & 7) + ((lane >> 3) & 1) * 8;
            int cB = kk * 16 + ((lane >> 4) << 3);
#pragma unroll
            for (int jp = 0; jp < 2; ++jp)
                ldsm4(bh[jp], aB + (uint32_t)(((rB + 16 * jp) * GST + cB) * 2));
#pragma unroll
            for (int i2 = 0; i2 < 4; ++i2)
#pragma unroll
                for (int jp = 0; jp < 2; ++jp) {
                    mma_f16(acc[i2][2 * jp],     ah[i2], bh[jp][0], bh[jp][2]);
                    mma_f16(acc[i2][2 * jp + 1], ah[i2], bh[jp][1], bh[jp][3]);
                }
        }
        __syncthreads();
    }

    int r0 = m0 + (lane >> 2);
    int cq = 2 * (lane & 3);
    if (mode == 0) {
#pragma unroll
        for (int i = 0; i < 4; ++i)
#pragma unroll
            for (int j = 0; j < 4; ++j) {
                int row = r0 + 16 * i;
                int col = n0 + 8 * j + cq;
                *reinterpret_cast<float2*>(Cf + (size_t)row * ldc + col) =
                    make_float2(acc[i][j][0], acc[i][j][1]);
                *reinterpret_cast<float2*>(Cf + (size_t)(row + 8) * ldc + col) =
                    make_float2(acc[i][j][2], acc[i][j][3]);
            }
    } else if (mode == 1) {
#pragma unroll
        for (int i = 0; i < 4; ++i)
#pragma unroll
            for (int j = 0; j < 4; ++j) {
                int row = r0 + 16 * i;
                int col = n0 + 8 * j + cq;
                *reinterpret_cast<uint32_t*>(Ch + (size_t)row * ldc + col) =
                    u32of(__floats2half2_rn(acc[i][j][0], acc[i][j][1]));
                *reinterpret_cast<uint32_t*>(Ch + (size_t)(row + 8) * ldc + col) =
                    u32of(__floats2half2_rn(acc[i][j][2], acc[i][j][3]));
            }
    } else {
        // RoPE fused: acc quads hold adjacent even/odd column pairs
#pragma unroll
        for (int i = 0; i < 4; ++i)
#pragma unroll
            for (int j = 0; j < 4; ++j) {
                int row = r0 + 16 * i;
                int col = n0 + 8 * j + cq;
                int pi = ((cb + col) & 63) >> 1;
                int gr = rbase + row;
                float c0 = rc[gr * 32 + pi], s0 = rs[gr * 32 + pi];
                float o0 = acc[i][j][0] * c0 - acc[i][j][1] * s0;
                float o1 = acc[i][j][0] * s0 + acc[i][j][1] * c0;
                *reinterpret_cast<uint32_t*>(Ch + (size_t)row * ldc + col) =
                    u32of(__floats2half2_rn(o0, o1));
                float c1 = rc[(gr + 8) * 32 + pi], s1 = rs[(gr + 8) * 32 + pi];
                o0 = acc[i][j][2] * c1 - acc[i][j][3] * s1;
                o1 = acc[i][j][2] * s1 + acc[i][j][3] * c1;
                *reinterpret_cast<uint32_t*>(Ch + (size_t)(row + 8) * ldc + col) =
                    u32of(__floats2half2_rn(o0, o1));
            }
    }
}

// QKV projection + fused RoPE: N = 2048 (Q) + 512 (K) + 512 (V)
__global__ __launch_bounds__(256) void qkv_hmma(const float* __restrict__ rc,
                                                const float* __restrict__ rs) {
    int bm = blockIdx.y * 128;
    int bn = blockIdx.x * 128;
    const __half* A = g_xh + (size_t)bm * DMODEL;
    const __half* B = g_wh + (size_t)bn * DMODEL;
    if (bn < 2048) {
        gemm_body(A, B, 2, nullptr, g_qh + (size_t)bm * DMODEL + bn, DMODEL,
                  rc, rs, bm, bn);
    } else if (bn < 2560) {
        gemm_body(A, B, 2, nullptr, g_kh + (size_t)bm * DKV + (bn - 2048), DKV,
                  rc, rs, bm, bn - 2048);
    } else {
        gemm_body(A, B, 1, nullptr, g_vh + (size_t)bm * DKV + (bn - 2560), DKV,
                  nullptr, nullptr, 0, 0);
    }
}

__global__ __launch_bounds__(256) void out_hmma(float* __restrict__ out) {
    int bm = blockIdx.y * 128;
    int bn = blockIdx.x * 128;
    gemm_body(g_ah + (size_t)bm * DMODEL, g_woh + (size_t)bn * DMODEL,
              0, out + (size_t)bm * DMODEL + bn, nullptr, DMODEL,
              nullptr, nullptr, 0, 0);
}

// ===========================================================================
// FA2-style causal GQA attention, single fp16, BQ=128 / BS=64,
// cp.async double-buffered K/V, triangle-balanced (qt=bi then 15-bi).
// 256 threads (8 warps), 16 q-rows/warp.
// ===========================================================================
#define AST 72   // smem row stride in halves (144B)
// sQ: 128*AST; sK0,sV0,sK1,sV1: 64*AST each
constexpr int ATTN_SMEM_BYTES = (128 * AST + 4 * 64 * AST) * 2;   // 55296

__global__ __launch_bounds__(256, 2) void attn_hmma() {
    extern __shared__ uint16_t sm16[];
    uint16_t* sQ = sm16;
    uint32_t aQ = smem_u32(sQ);
    uint32_t aKV0 = aQ + 128 * AST * 2;                 // K0,V0
    uint32_t aKV1 = aKV0 + 2 * 64 * AST * 2;            // K1,V1

    int tid = threadIdx.x;
    int lane = tid & 31;
    int w = tid >> 5;
    int h = blockIdx.y;
    int kvh = h >> 2;
    const float SCALE = 0.125f;

    for (int pass = 0; pass < 2; ++pass) {
        int qt = pass == 0 ? (int)blockIdx.x : 15 - (int)blockIdx.x;

        __syncthreads();   // prior pass fully done before overwriting sQ
        // Load Q tile (fp16, 128 x 64)
#pragma unroll
        for (int it = 0; it < 4; ++it) {
            int slot = tid + it * 256;       // 1024 slots: 128 rows x 8 chunks
            int r = slot >> 3;
            int q = slot & 7;
            const __half* src =
                g_qh + (size_t)(qt * 128 + r) * DMODEL + h * DHEAD + q * 8;
            *reinterpret_cast<uint4*>(sQ + r * AST + q * 8) =
                *reinterpret_cast<const uint4*>(src);
        }
        __syncthreads();

        // Q fragments in registers (warp w owns rows 16w..16w+15)
        uint32_t qf[4][4];
        {
            int rQ = 16 * w + (lane & 15);
            int cF = ((lane >> 4) << 3);
#pragma unroll
            for (int kk = 0; kk < 4; ++kk)
                ldsm4(qf[kk], aQ + (uint32_t)((rQ * AST + cF + 16 * kk) * 2));
        }

        float m0 = -1e30f, m1 = -1e30f, l0 = 0.0f, l1 = 0.0f;
        float oac[8][4];
#pragma unroll
        for (int j = 0; j < 8; ++j)
#pragma unroll
            for (int q = 0; q < 4; ++q) oac[j][q] = 0.0f;

        int nst = 2 * qt + 2;

        // K/V stage loader (cp.async, 1024 slots: K 512 + V 512)
        auto load_kv = [&](int st, uint32_t dbase) {
#pragma unroll
            for (int it = 0; it < 4; ++it) {
                int slot = tid + it * 256;
                int t = slot >> 9;           // 0 = K, 1 = V
                int r = (slot >> 3) & 63;
                int q = slot & 7;
                const __half* src = (t ? g_vh : g_kh) +
                    (size_t)(st * 64 + r) * DKV + kvh * DHEAD + q * 8;
                uint32_t dst = dbase + (uint32_t)(t * 64 * AST + r * AST + q * 8) * 2;
                cp_async16(dst, src);
            }
        };

        load_kv(0, aKV0);
        CP_COMMIT();

        for (int st = 0; st < nst; ++st) {
            uint32_t aK = (st & 1) ? aKV1 : aKV0;
            uint32_t aV = aK + 64 * AST * 2;
            CP_WAIT(0);
            __syncthreads();
            if (st + 1 < nst) {
                load_kv(st + 1, (st & 1) ? aKV0 : aKV1);
                CP_COMMIT();
            }

            // ---- S = Q K^T ----
            float sa[8][4];
#pragma unroll
            for (int j = 0; j < 8; ++j)
#pragma unroll
                for (int q = 0; q < 4; ++q) sa[j][q] = 0.0f;

            int rB = (lane & 7) + ((lane >> 3) & 1) * 8;
            int cF = ((lane >> 4) << 3);
#pragma unroll
            for (int kk = 0; kk < 4; ++kk) {
                uint32_t kb[4][4];
#pragma unroll
                for (int jp = 0; jp < 4; ++jp)
                    ldsm4(kb[jp], aK + (uint32_t)(((rB + 16 * jp) * AST + cF + 16 * kk) * 2));
#pragma unroll
                for (int jp = 0; jp < 4; ++jp) {
                    mma_f16(sa[2 * jp],     qf[kk], kb[jp][0], kb[jp][2]);
                    mma_f16(sa[2 * jp + 1], qf[kk], kb[jp][1], kb[jp][3]);
                }
            }

            // ---- causal mask (tiles st=2qt and 2qt+1 touch the diagonal) ----
            if (st >= 2 * qt) {
                int dd = 16 * w + (lane >> 2) - (st - 2 * qt) * 64;
#pragma unroll
                for (int j = 0; j < 8; ++j) {
                    int c = 8 * j + 2 * (lane & 3);
                    if (c > dd)         sa[j][0] = -1e30f;
                    if (c + 1 > dd)     sa[j][1] = -1e30f;
                    if (c > dd + 8)     sa[j][2] = -1e30f;
                    if (c + 1 > dd + 8) sa[j][3] = -1e30f;
                }
            }

            // ---- online softmax ----
            float rmax0 = -1e30f, rmax1 = -1e30f;
#pragma unroll
            for (int j = 0; j < 8; ++j) {
                rmax0 = fmaxf(rmax0, fmaxf(sa[j][0], sa[j][1]));
                rmax1 = fmaxf(rmax1, fmaxf(sa[j][2], sa[j][3]));
            }
#pragma unroll
            for (int off = 1; off < 4; off <<= 1) {
                rmax0 = fmaxf(rmax0, __shfl_xor_sync(0xffffffffu, rmax0, off));
                rmax1 = fmaxf(rmax1, __shfl_xor_sync(0xffffffffu, rmax1, off));
            }
            float mn0 = fmaxf(m0, SCALE * rmax0);
            float mn1 = fmaxf(m1, SCALE * rmax1);
            float al0 = __expf(m0 - mn0);
            float al1 = __expf(m1 - mn1);

            uint32_t pa[4][4];
            float rs0 = 0.0f, rs1 = 0.0f;
#pragma unroll
            for (int j = 0; j < 8; ++j) {
                float p0 = __expf(fmaf(SCALE, sa[j][0], -mn0));
                float p1 = __expf(fmaf(SCALE, sa[j][1], -mn0));
                float p2 = __expf(fmaf(SCALE, sa[j][2], -mn1));
                float p3 = __expf(fmaf(SCALE, sa[j][3], -mn1));
                rs0 += p0 + p1;
                rs1 += p2 + p3;
                pa[j >> 1][(j & 1) ? 2 : 0] = u32of(__floats2half2_rn(p0, p1));
                pa[j >> 1][(j & 1) ? 3 : 1] = u32of(__floats2half2_rn(p2, p3));
            }
#pragma unroll
            for (int off = 1; off < 4; off <<= 1) {
                rs0 += __shfl_xor_sync(0xffffffffu, rs0, off);
                rs1 += __shfl_xor_sync(0xffffffffu, rs1, off);
            }
            l0 = l0 * al0 + rs0;
            l1 = l1 * al1 + rs1;
            m0 = mn0;
            m1 = mn1;
#pragma unroll
            for (int j = 0; j < 8; ++j) {
                oac[j][0] *= al0;
                oac[j][1] *= al0;
                oac[j][2] *= al1;
                oac[j][3] *= al1;
            }

            // ---- O += P V ----
#pragma unroll
            for (int ks = 0; ks < 4; ++ks) {
                uint32_t vh[4][4];
                int row = 16 * ks + (lane & 7) + ((lane >> 3) & 1) * 8;
#pragma unroll
                for (int jp = 0; jp < 4; ++jp) {
                    int col = 16 * jp + ((lane >> 4) << 3);
                    ldsm4t(vh[jp], aV + (uint32_t)((row * AST + col) * 2));
                }
#pragma unroll
                for (int jp = 0; jp < 4; ++jp) {
                    mma_f16(oac[2 * jp],     pa[ks], vh[jp][0], vh[jp][1]);
                    mma_f16(oac[2 * jp + 1], pa[ks], vh[jp][2], vh[jp][3]);
                }
            }
        }

        // Epilogue: normalize, fp16 out for out-projection
        float inv0 = 1.0f / l0;
        float inv1 = 1.0f / l1;
        int row = qt * 128 + 16 * w + (lane >> 2);
        size_t ob = (size_t)row * DMODEL + h * DHEAD;
#pragma unroll
        for (int j = 0; j < 8; ++j) {
            int col = 8 * j + 2 * (lane & 3);
            *reinterpret_cast<uint32_t*>(g_ah + ob + col) =
                u32of(__floats2half2_rn(oac[j][0] * inv0, oac[j][1] * inv0));
            *reinterpret_cast<uint32_t*>(g_ah + ob + (size_t)8 * DMODEL + col) =
                u32of(__floats2half2_rn(oac[j][2] * inv1, oac[j][3] * inv1));
        }
    }
}

// ---------------------------------------------------------------------------
extern "C" void kernel_launch(void* const* d_in, const int* in_sizes, int n_in,
                              void* d_out, int out_size) {
    const float* x  = (const float*)d_in[0];
    const float* Wq = (const float*)d_in[1];
    const float* Wk = (const float*)d_in[2];
    const float* Wv = (const float*)d_in[3];
    const float* Wo = (const float*)d_in[4];
    const float* rc = (const float*)d_in[5];
    const float* rs = (const float*)d_in[6];
    float* out = (float*)d_out;

    static bool attrs_set = false;
    if (!attrs_set) {
        cudaFuncSetAttribute(attn_hmma, cudaFuncAttributeMaxDynamicSharedMemorySize,
                             ATTN_SMEM_BYTES);
        cudaFuncSetAttribute(qkv_hmma, cudaFuncAttributeMaxDynamicSharedMemorySize,
                             GEMM_SMEM_BYTES);
        cudaFuncSetAttribute(out_hmma, cudaFuncAttributeMaxDynamicSharedMemorySize,
                             GEMM_SMEM_BYTES);
        attrs_set = true;
    }

    // 0) One fused conversion kernel (x, Wq, Wk, Wv, Wo -> fp16)
    cvt_all_kernel<<<(2 * N4X + 2 * N4K + N4X) / 256, 256>>>(x, Wq, Wk, Wv, Wo);

    // 1) Fused QKV projection + RoPE epilogue (single fp16 HMMA)
    qkv_hmma<<<dim3(24, 16), 256, GEMM_SMEM_BYTES>>>(rc, rs);

    // 2) Causal GQA attention (single fp16, BQ=128, cp.async double buffer)
    attn_hmma<<<dim3(8, HQ), 256, ATTN_SMEM_BYTES>>>();

    // 3) Output projection
    out_hmma<<<dim3(16, 16), 256, GEMM_SMEM_BYTES>>>(out);
}